// round 7
// baseline (speedup 1.0000x reference)
#include <cuda_runtime.h>
#include <cuda_bf16.h>
#include <stdint.h>
#include <math.h>

// Shapes (fixed for this problem)
#define B_  16
#define S_  512
#define E_  128
#define T_  640      // S_ + E_
#define D_  768
#define H_  12
#define DH_ 64
#define FF_ 3072
#define NT_ (B_*T_) // 10240

typedef unsigned int       u32;
typedef unsigned long long u64;

// ---------------- scratch (__device__ globals, all fp32/tf32) ----------------
__device__ float g_wordr[(size_t)B_*S_*D_];
__device__ float g_entr [(size_t)B_*E_*D_];
__device__ float g_q1 [(size_t)NT_*D_];
__device__ float g_q2 [(size_t)NT_*D_];
__device__ float g_k  [(size_t)NT_*D_];
__device__ float g_v  [(size_t)NT_*D_];
__device__ float g_vt [(size_t)NT_*D_];      // [b*H+h][d][t]
__device__ float g_ctx[(size_t)NT_*D_];
__device__ float g_ao [(size_t)NT_*D_];
__device__ float g_tmp[(size_t)NT_*D_];
__device__ float g_inter[(size_t)NT_*FF_];

// transposed tf32-rounded weights ([N,K] row-major)
__device__ float g_wpw[4*D_*D_];   // word: q | w2e | k | v
__device__ float g_wpe[4*D_*D_];   // ent:  e2w | e2e | k | v
__device__ float g_wao[D_*D_];
__device__ float g_wi [FF_*D_];
__device__ float g_wo [D_*FF_];

struct DestPack { float* y; const float* bias; };
struct Dest4 { DestPack d[4]; };

// ---------------- PTX helpers ----------------------------------------------
__device__ __forceinline__ u32 smem_u32(const void* p) {
    u32 a;
    asm("{ .reg .u64 t; cvta.to.shared.u64 t, %1; cvt.u32.u64 %0, t; }" : "=r"(a) : "l"(p));
    return a;
}
__device__ __forceinline__ void cpa16(u32 s, const void* g) {
    asm volatile("cp.async.cg.shared.global [%0], [%1], 16;" :: "r"(s), "l"(g));
}
__device__ __forceinline__ void ldsm4(u32 addr, u32& r0, u32& r1, u32& r2, u32& r3) {
    asm volatile("ldmatrix.sync.aligned.m8n8.x4.shared.b16 {%0,%1,%2,%3}, [%4];"
                 : "=r"(r0), "=r"(r1), "=r"(r2), "=r"(r3) : "r"(addr));
}
__device__ __forceinline__ void mma_tf32(float* c, const u32* a, u32 b0, u32 b1) {
    asm volatile(
        "mma.sync.aligned.m16n8k8.row.col.f32.tf32.tf32.f32 "
        "{%0,%1,%2,%3}, {%4,%5,%6,%7}, {%8,%9}, {%0,%1,%2,%3};"
        : "+f"(c[0]), "+f"(c[1]), "+f"(c[2]), "+f"(c[3])
        : "r"(a[0]), "r"(a[1]), "r"(a[2]), "r"(a[3]), "r"(b0), "r"(b1));
}
__device__ __forceinline__ float to_tf32(float x) {
    u32 r; asm("cvt.rna.tf32.f32 %0, %1;" : "=r"(r) : "f"(x));
    return __uint_as_float(r);
}
__device__ __forceinline__ float fexp(float x) {
    x = fmaxf(x, -80.f);
    float y = x * 1.4426950408889634f;
    int n = __float2int_rn(y);
    float f = y - (float)n;
    float p = 1.33336e-3f;
    p = fmaf(p, f, 9.61813e-3f);
    p = fmaf(p, f, 5.5504109e-2f);
    p = fmaf(p, f, 2.4022651e-1f);
    p = fmaf(p, f, 6.9314718e-1f);
    p = fmaf(p, f, 1.0f);
    return p * __int_as_float((n + 127) << 23);
}

// ---------------- weight transpose (+tf32 round) -----------------------------
__global__ __launch_bounds__(256)
void wconv(const float* __restrict__ W, float* __restrict__ Wt, int K, int N)
{
    __shared__ float t[32][33];
    const int n0 = blockIdx.x * 32, k0 = blockIdx.y * 32;
    const int tx = threadIdx.x & 31, ty = threadIdx.x >> 5;
#pragma unroll
    for (int i = 0; i < 4; i++)
        t[ty + i*8][tx] = W[(size_t)(k0 + ty + i*8) * N + n0 + tx];
    __syncthreads();
#pragma unroll
    for (int i = 0; i < 4; i++)
        Wt[(size_t)(n0 + ty + i*8) * K + k0 + tx] = to_tf32(t[tx][ty + i*8]);
}

// ---------------- tf32 rounding copy -----------------------------------------
__global__ __launch_bounds__(256)
void rconv(const float* __restrict__ x, float* __restrict__ y)
{
    size_t i = (size_t)blockIdx.x * 256 + threadIdx.x;
    y[i] = to_tf32(x[i]);
}

// ---------------- V transpose: [b][t][h*64+d] -> [(b*H+h)*64+d][t] -----------
__global__ __launch_bounds__(256)
void vtrans(const float* __restrict__ v, float* __restrict__ vt)
{
    __shared__ float t[32][33];
    const int bh = blockIdx.z;
    const int b = bh / H_, h = bh % H_;
    const int t0 = blockIdx.x * 32, d0 = blockIdx.y * 32;
    const int tx = threadIdx.x & 31, ty = threadIdx.x >> 5;
#pragma unroll
    for (int i = 0; i < 4; i++)
        t[ty + i*8][tx] = v[(size_t)(b * T_ + t0 + ty + i*8) * D_ + h * DH_ + d0 + tx];
    __syncthreads();
#pragma unroll
    for (int i = 0; i < 4; i++)
        vt[((size_t)bh * DH_ + d0 + ty + i*8) * T_ + t0 + tx] = t[tx][ty + i*8];
}

// ---------------- TF32 GEMM (128x128 CTA, 32x64 warp, 3-stage) ---------------
// Y[m,n] = A[m,:] @ Bt[n,:] + bias ; dest by n / nsplit; remap rows by seg/rowoff.
// act==0: fp32 out. act==1: GELU + tf32-round. act==2: tf32-round.
#define AROW_BY  80                   // 64B data + 16 pad (bank step 20)
#define TILE_BY  (128*AROW_BY)        // 10240
#define STG_BY   (2*TILE_BY)          // 20480
#define SMEM_DYN (3*STG_BY)           // 61440

__global__ __launch_bounds__(256)
void gemm_tc(const float* __restrict__ A, const float* __restrict__ Bt,
             Dest4 dp, int M, int N, int K, int nsplit, int seg, int rowoff, int act)
{
    extern __shared__ char smem[];
    const u32 sb = smem_u32(smem);
    const int tid  = threadIdx.x;
    const int lane = tid & 31;
    const int wid  = tid >> 5;
    const int wm   = wid >> 1;     // 0..3
    const int wn   = wid & 1;      // 0..1
    const int n0 = blockIdx.x * 128;
    const int m0 = blockIdx.y * 128;
    const int nk = K / 16;

    auto load_chunk = [&](int s, int kc) {
        const int k0c = kc * 16;
        const u32 stg = sb + (u32)s * STG_BY;
#pragma unroll
        for (int i = 0; i < 4; i++) {
            int idx = tid + i * 256;      // 0..1023
            int r   = idx >> 2;
            int c16 = idx & 3;
            const float* g; u32 soff;
            if (r < 128) { g = A  + (size_t)(m0 + r) * K;       soff = (u32)(r * AROW_BY); }
            else         { g = Bt + (size_t)(n0 + r - 128) * K; soff = (u32)TILE_BY + (u32)((r - 128) * AROW_BY); }
            cpa16(stg + soff + (u32)(c16 * 16), g + k0c + c16 * 4);
        }
        asm volatile("cp.async.commit_group;" ::: "memory");
    };

    float acc[2][8][4];
#pragma unroll
    for (int mt = 0; mt < 2; mt++)
#pragma unroll
        for (int nt = 0; nt < 8; nt++)
#pragma unroll
            for (int j = 0; j < 4; j++) acc[mt][nt][j] = 0.f;

    const u32 frag_row = (u32)(lane & 15);
    const u32 frag_col = (u32)((lane >> 4) << 4);

    load_chunk(0, 0);
    load_chunk(1, 1);

    for (int kc = 0; kc < nk; kc++) {
        const int s = kc % 3;
        if (kc + 2 < nk) {
            load_chunk((kc + 2) % 3, kc + 2);
            asm volatile("cp.async.wait_group 2;" ::: "memory");
        } else if (kc + 1 < nk) {
            asm volatile("cp.async.wait_group 1;" ::: "memory");
        } else {
            asm volatile("cp.async.wait_group 0;" ::: "memory");
        }
        __syncthreads();

        const u32 aBase = sb + (u32)s * STG_BY;
        const u32 bBase = aBase + TILE_BY;

#pragma unroll
        for (int ks = 0; ks < 2; ks++) {           // two k8 steps
            const u32 kByte = (u32)(ks * 32) + frag_col;
            u32 a[2][4], bb[4][4];
#pragma unroll
            for (int mt = 0; mt < 2; mt++) {
                u32 ro = (u32)(wm * 32 + mt * 16) + frag_row;
                ldsm4(aBase + ro * AROW_BY + kByte, a[mt][0], a[mt][1], a[mt][2], a[mt][3]);
            }
#pragma unroll
            for (int np = 0; np < 4; np++) {
                u32 ro = (u32)(wn * 64 + np * 16) + frag_row;
                ldsm4(bBase + ro * AROW_BY + kByte, bb[np][0], bb[np][1], bb[np][2], bb[np][3]);
            }
#pragma unroll
            for (int mt = 0; mt < 2; mt++)
#pragma unroll
                for (int nt = 0; nt < 8; nt++) {
                    int np = nt >> 1, sel = nt & 1;
                    mma_tf32(acc[mt][nt], a[mt], bb[np][sel], bb[np][sel + 2]);
                }
        }
        __syncthreads();
    }

    // epilogue
    const int di = n0 / nsplit;
    float* Y  = dp.d[di].y;
    const float* bias = dp.d[di].bias;
    const int ncol_off = di * nsplit;

#pragma unroll
    for (int mt = 0; mt < 2; mt++) {
#pragma unroll
        for (int half = 0; half < 2; half++) {
            int mlog = m0 + wm * 32 + mt * 16 + (lane >> 2) + half * 8;
            size_t phys = (size_t)(mlog / seg) * T_ + (mlog % seg) + rowoff;
#pragma unroll
            for (int nt = 0; nt < 8; nt++) {
                int col = n0 + wn * 64 + nt * 8 + (lane & 3) * 2 - ncol_off;
                float v0 = acc[mt][nt][half * 2 + 0] + bias[col + 0];
                float v1 = acc[mt][nt][half * 2 + 1] + bias[col + 1];
                if (act == 1) {
                    v0 = 0.5f * v0 * (1.0f + erff(v0 * 0.70710678f));
                    v1 = 0.5f * v1 * (1.0f + erff(v1 * 0.70710678f));
                }
                if (act != 0) { v0 = to_tf32(v0); v1 = to_tf32(v1); }
                *(float2*)(Y + phys * (size_t)nsplit + col) = make_float2(v0, v1);
            }
        }
    }
}

// ---------------- TF32 flash attention ---------------------------------------
// 128 q/block, 5 key tiles of 128. Q/K tiles [128][64 fp32] stride 272B;
// V^T tile [64][128 fp32] stride 528B. All strides 16B-aligned, conflict-free.
#define QROW 272
#define QT   (128*QROW)              // 34816
#define VROW 528
#define A_Q1 0
#define A_Q2 (QT)
#define A_K  (2*QT)
#define A_VT (3*QT)
#define A_MS (3*QT + 64*VROW)        // 138240
#define ATT_SMEM (A_MS + 512)        // 138752

__global__ __launch_bounds__(256)
void attn_tc(const float* __restrict__ q1, const float* __restrict__ q2,
             const float* __restrict__ k,  const float* __restrict__ vt,
             const float* __restrict__ mask, float* __restrict__ ctx)
{
    extern __shared__ char smem[];
    const u32 sb = smem_u32(smem);
    float* maskS = (float*)(smem + A_MS);

    const int b  = blockIdx.z;
    const int h  = blockIdx.y;
    const int q0 = blockIdx.x * 128;
    const int tid  = threadIdx.x;
    const int lane = tid & 31;
    const int w    = tid >> 5;

    const u32 frag_row = (u32)(lane & 15);
    const u32 frag_col = (u32)((lane >> 4) << 4);

    // Q tiles (q1, q2): 128 rows x 256B each
    {
        const float* srcQ[2] = { q1, q2 };
#pragma unroll
        for (int i = 0; i < 16; i++) {
            int idx = tid + i * 256;          // 0..4095
            int arr = idx >> 11;              // 0..1
            int rr  = (idx >> 4) & 127;
            int ch  = idx & 15;
            cpa16(sb + (u32)(arr * QT + rr * QROW + ch * 16),
                  srcQ[arr] + (size_t)(b * T_ + q0 + rr) * D_ + h * DH_ + ch * 4);
        }
        asm volatile("cp.async.commit_group;" ::: "memory");
    }

    float Oa[8][4];
#pragma unroll
    for (int od = 0; od < 8; od++)
#pragma unroll
        for (int j = 0; j < 4; j++) Oa[od][j] = 0.f;
    float m0 = -1e30f, m1 = -1e30f, l0 = 0.f, l1 = 0.f;

    for (int kt = 0; kt < 5; kt++) {
        __syncthreads();
        {
#pragma unroll
            for (int i = 0; i < 8; i++) {      // K tile: 128 rows x 256B
                int idx = tid + i * 256;
                int rr  = (idx >> 4) & 127;
                int ch  = idx & 15;
                cpa16(sb + (u32)(A_K + rr * QROW + ch * 16),
                      k + (size_t)(b * T_ + kt * 128 + rr) * D_ + h * DH_ + ch * 4);
            }
#pragma unroll
            for (int i = 0; i < 8; i++) {      // V^T tile: 64 rows x 512B
                int idx = tid + i * 256;
                int rr  = (idx >> 5) & 63;
                int ch  = idx & 31;
                cpa16(sb + (u32)(A_VT + rr * VROW + ch * 16),
                      vt + ((size_t)(b * H_ + h) * DH_ + rr) * T_ + kt * 128 + ch * 4);
            }
            if (tid < 128) maskS[tid] = mask[b * T_ + kt * 128 + tid];
            asm volatile("cp.async.commit_group;" ::: "memory");
            asm volatile("cp.async.wait_group 0;" ::: "memory");
        }
        __syncthreads();

        const u32 qb = sb + (u32)((kt < 4) ? A_Q1 : A_Q2);

        // ---- scores ----
        float sc_[16][4];
#pragma unroll
        for (int nt = 0; nt < 16; nt++)
#pragma unroll
            for (int j = 0; j < 4; j++) sc_[nt][j] = 0.f;

#pragma unroll
        for (int ks = 0; ks < 8; ks++) {       // 8 k8 steps over DH=64
            const u32 kByte = (u32)(ks * 32) + frag_col;
            u32 a[4], bh[8][4];
            u32 ro = (u32)(w * 16) + frag_row;
            ldsm4(qb + ro * QROW + kByte, a[0], a[1], a[2], a[3]);
#pragma unroll
            for (int np = 0; np < 8; np++) {
                u32 kr = (u32)(np * 16) + frag_row;
                ldsm4(sb + A_K + kr * QROW + kByte, bh[np][0], bh[np][1], bh[np][2], bh[np][3]);
            }
#pragma unroll
            for (int nt = 0; nt < 16; nt++) {
                int np = nt >> 1, sel = nt & 1;
                mma_tf32(sc_[nt], a, bh[np][sel], bh[np][sel + 2]);
            }
        }

        // ---- online softmax ----
        float rmax0 = -1e30f, rmax1 = -1e30f;
#pragma unroll
        for (int nt = 0; nt < 16; nt++) {
            int cbase = nt * 8 + (lane & 3) * 2;
            float mk0 = maskS[cbase], mk1 = maskS[cbase + 1];
            sc_[nt][0] = fmaf(sc_[nt][0], 0.125f, mk0);
            sc_[nt][1] = fmaf(sc_[nt][1], 0.125f, mk1);
            sc_[nt][2] = fmaf(sc_[nt][2], 0.125f, mk0);
            sc_[nt][3] = fmaf(sc_[nt][3], 0.125f, mk1);
            rmax0 = fmaxf(rmax0, fmaxf(sc_[nt][0], sc_[nt][1]));
            rmax1 = fmaxf(rmax1, fmaxf(sc_[nt][2], sc_[nt][3]));
        }
        rmax0 = fmaxf(rmax0, __shfl_xor_sync(0xffffffffu, rmax0, 1));
        rmax0 = fmaxf(rmax0, __shfl_xor_sync(0xffffffffu, rmax0, 2));
        rmax1 = fmaxf(rmax1, __shfl_xor_sync(0xffffffffu, rmax1, 1));
        rmax1 = fmaxf(rmax1, __shfl_xor_sync(0xffffffffu, rmax1, 2));

        float mn0 = fmaxf(m0, rmax0), mn1 = fmaxf(m1, rmax1);
        float f0 = fexp(m0 - mn0), f1 = fexp(m1 - mn1);
        float rs0 = 0.f, rs1 = 0.f;
#pragma unroll
        for (int nt = 0; nt < 16; nt++) {
            sc_[nt][0] = fexp(sc_[nt][0] - mn0);
            sc_[nt][1] = fexp(sc_[nt][1] - mn0);
            sc_[nt][2] = fexp(sc_[nt][2] - mn1);
            sc_[nt][3] = fexp(sc_[nt][3] - mn1);
            rs0 += sc_[nt][0] + sc_[nt][1];
            rs1 += sc_[nt][2] + sc_[nt][3];
        }
        rs0 += __shfl_xor_sync(0xffffffffu, rs0, 1);
        rs0 += __shfl_xor_sync(0xffffffffu, rs0, 2);
        rs1 += __shfl_xor_sync(0xffffffffu, rs1, 1);
        rs1 += __shfl_xor_sync(0xffffffffu, rs1, 2);
        l0 = l0 * f0 + rs0;
        l1 = l1 * f1 + rs1;
        m0 = mn0; m1 = mn1;
#pragma unroll
        for (int od = 0; od < 8; od++) {
            Oa[od][0] *= f0; Oa[od][1] *= f0;
            Oa[od][2] *= f1; Oa[od][3] *= f1;
        }

        // ---- P @ V (tf32; P rearranged via shuffles into A-fragments) ----
        const int t2 = lane & 3;
        const int srcA = (lane & ~3) | (t2 >> 1);
        const int srcB = srcA + 2;
        const bool odd = (t2 & 1) != 0;
#pragma unroll
        for (int kk = 0; kk < 16; kk++) {      // 16 k8 steps over 128 keys
            float c0 = to_tf32(sc_[kk][0]);
            float c1 = to_tf32(sc_[kk][1]);
            float c2 = to_tf32(sc_[kk][2]);
            float c3 = to_tf32(sc_[kk][3]);
            float y0 = __shfl_sync(0xffffffffu, c0, srcA);
            float y1 = __shfl_sync(0xffffffffu, c1, srcA);
            float y2 = __shfl_sync(0xffffffffu, c2, srcA);
            float y3 = __shfl_sync(0xffffffffu, c3, srcA);
            float z0 = __shfl_sync(0xffffffffu, c0, srcB);
            float z1 = __shfl_sync(0xffffffffu, c1, srcB);
            float z2 = __shfl_sync(0xffffffffu, c2, srcB);
            float z3 = __shfl_sync(0xffffffffu, c3, srcB);
            u32 aP[4];
            aP[0] = __float_as_uint(odd ? y1 : y0);   // P[g][t]
            aP[1] = __float_as_uint(odd ? y3 : y2);   // P[g+8][t]
            aP[2] = __float_as_uint(odd ? z1 : z0);   // P[g][t+4]
            aP[3] = __float_as_uint(odd ? z3 : z2);   // P[g+8][t+4]

            const u32 kByte = (u32)(kk * 32) + frag_col;
#pragma unroll
            for (int nd = 0; nd < 4; nd++) {
                u32 r0, r1, r2, r3;
                ldsm4(sb + A_VT + ((u32)(nd * 16) + frag_row) * VROW + kByte, r0, r1, r2, r3);
                mma_tf32(Oa[nd * 2],     aP, r0, r2);
                mma_tf32(Oa[nd * 2 + 1], aP, r1, r3);
            }
        }
    }

    // ---- epilogue ----
    float inv0 = 1.f / l0, inv1 = 1.f / l1;
    int qa = q0 + w * 16 + (lane >> 2);
    int qb2 = qa + 8;
    size_t baseA = (size_t)(b * T_ + qa) * D_ + h * DH_;
    size_t baseB = (size_t)(b * T_ + qb2) * D_ + h * DH_;
#pragma unroll
    for (int od = 0; od < 8; od++) {
        int col = od * 8 + (lane & 3) * 2;
        *(float2*)(ctx + baseA + col) =
            make_float2(to_tf32(Oa[od][0] * inv0), to_tf32(Oa[od][1] * inv0));
        *(float2*)(ctx + baseB + col) =
            make_float2(to_tf32(Oa[od][2] * inv1), to_tf32(Oa[od][3] * inv1));
    }
}

// ---------------- residual + LayerNorm ---------------------------------------
__global__ __launch_bounds__(256)
void ln_kernel(const float* __restrict__ raw,
               const float* __restrict__ rw, const float* __restrict__ re,
               const float* __restrict__ rfull, int use_full,
               const float* __restrict__ gm, const float* __restrict__ bt,
               float* __restrict__ out, int final_mode, int round_out)
{
    const int row = blockIdx.x;
    const int b = row / T_, t = row % T_;
    const float* rp = use_full
        ? rfull + (size_t)row * D_
        : (t < S_ ? rw + ((size_t)(b * S_ + t)) * D_
                  : re + ((size_t)(b * E_ + t - S_)) * D_);
    const float* x = raw + (size_t)row * D_;

    float vv[3];
    float s = 0.f, sq = 0.f;
#pragma unroll
    for (int i = 0; i < 3; i++) {
        int c = threadIdx.x + i * 256;
        float val = x[c] + rp[c];
        vv[i] = val;
        s += val;
        sq += val * val;
    }
    const int lane = threadIdx.x & 31, w = threadIdx.x >> 5;
#pragma unroll
    for (int o = 16; o; o >>= 1) {
        s  += __shfl_xor_sync(0xffffffffu, s,  o);
        sq += __shfl_xor_sync(0xffffffffu, sq, o);
    }
    __shared__ float ws[8], wq[8];
    __shared__ float sm, sv;
    if (lane == 0) { ws[w] = s; wq[w] = sq; }
    __syncthreads();
    if (threadIdx.x == 0) {
        float ts = 0.f, tq = 0.f;
#pragma unroll
        for (int i = 0; i < 8; i++) { ts += ws[i]; tq += wq[i]; }
        float mean = ts * (1.f / D_);
        sm = mean;
        sv = rsqrtf(tq * (1.f / D_) - mean * mean + 1e-12f);
    }
    __syncthreads();
    const float mean = sm, inv = sv;

    float* o = final_mode
        ? (t < S_ ? out + ((size_t)(b * S_ + t)) * D_
                  : out + (size_t)B_ * S_ * D_ + ((size_t)(b * E_ + t - S_)) * D_)
        : out + (size_t)row * D_;
#pragma unroll
    for (int i = 0; i < 3; i++) {
        int c = threadIdx.x + i * 256;
        float y = (vv[i] - mean) * inv * gm[c] + bt[c];
        o[c] = round_out ? to_tf32(y) : y;
    }
}

// ---------------- host -------------------------------------------------------
extern "C" void kernel_launch(void* const* d_in, const int* in_sizes, int n_in,
                              void* d_out, int out_size)
{
    const float* word  = (const float*)d_in[0];
    const float* ent   = (const float*)d_in[1];
    const float* mask  = (const float*)d_in[2];
    const float* W_q   = (const float*)d_in[3],  *b_q    = (const float*)d_in[4];
    const float* W_k   = (const float*)d_in[5],  *b_k    = (const float*)d_in[6];
    const float* W_v   = (const float*)d_in[7],  *b_v    = (const float*)d_in[8];
    const float* W_w2e = (const float*)d_in[9],  *b_w2e  = (const float*)d_in[10];
    const float* W_e2w = (const float*)d_in[11], *b_e2w  = (const float*)d_in[12];
    const float* W_e2e = (const float*)d_in[13], *b_e2e  = (const float*)d_in[14];
    const float* W_ao  = (const float*)d_in[15], *b_ao   = (const float*)d_in[16];
    const float* gm_ao = (const float*)d_in[17], *bt_ao  = (const float*)d_in[18];
    const float* W_i   = (const float*)d_in[19], *b_i    = (const float*)d_in[20];
    const float* W_o   = (const float*)d_in[21], *b_o    = (const float*)d_in[22];
    const float* gm_o  = (const float*)d_in[23], *bt_o   = (const float*)d_in[24];

    void* p;
    cudaGetSymbolAddress(&p, g_wordr); float* d_wordr = (float*)p;
    cudaGetSymbolAddress(&p, g_entr);  float* d_entr  = (float*)p;
    cudaGetSymbolAddress(&p, g_q1);    float* d_q1    = (float*)p;
    cudaGetSymbolAddress(&p, g_q2);    float* d_q2    = (float*)p;
    cudaGetSymbolAddress(&p, g_k);     float* d_k     = (float*)p;
    cudaGetSymbolAddress(&p, g_v);     float* d_v     = (float*)p;
    cudaGetSymbolAddress(&p, g_vt);    float* d_vt    = (float*)p;
    cudaGetSymbolAddress(&p, g_ctx);   float* d_ctx   = (float*)p;
    cudaGetSymbolAddress(&p, g_ao);    float* d_ao    = (float*)p;
    cudaGetSymbolAddress(&p, g_tmp);   float* d_tmp   = (float*)p;
    cudaGetSymbolAddress(&p, g_inter); float* d_inter = (float*)p;

    float *wpw, *wpe, *wao, *wi, *wo;
    cudaGetSymbolAddress(&p, g_wpw); wpw = (float*)p;
    cudaGetSymbolAddress(&p, g_wpe); wpe = (float*)p;
    cudaGetSymbolAddress(&p, g_wao); wao = (float*)p;
    cudaGetSymbolAddress(&p, g_wi);  wi  = (float*)p;
    cudaGetSymbolAddress(&p, g_wo);  wo  = (float*)p;

    cudaFuncSetAttribute(gemm_tc, cudaFuncAttributeMaxDynamicSharedMemorySize, SMEM_DYN);
    cudaFuncSetAttribute(attn_tc, cudaFuncAttributeMaxDynamicSharedMemorySize, ATT_SMEM);

    const dim3 thr(256);
    const int MW = B_ * S_;
    const int ME = B_ * E_;
    const size_t WSLICE = (size_t)D_ * D_;

    // weight transpose + tf32 round
    wconv<<<dim3(D_/32,  D_/32),  thr>>>(W_q,   wpw + 0*WSLICE, D_, D_);
    wconv<<<dim3(D_/32,  D_/32),  thr>>>(W_w2e, wpw + 1*WSLICE, D_, D_);
    wconv<<<dim3(D_/32,  D_/32),  thr>>>(W_k,   wpw + 2*WSLICE, D_, D_);
    wconv<<<dim3(D_/32,  D_/32),  thr>>>(W_v,   wpw + 3*WSLICE, D_, D_);
    wconv<<<dim3(D_/32,  D_/32),  thr>>>(W_e2w, wpe + 0*WSLICE, D_, D_);
    wconv<<<dim3(D_/32,  D_/32),  thr>>>(W_e2e, wpe + 1*WSLICE, D_, D_);
    wconv<<<dim3(D_/32,  D_/32),  thr>>>(W_k,   wpe + 2*WSLICE, D_, D_);
    wconv<<<dim3(D_/32,  D_/32),  thr>>>(W_v,   wpe + 3*WSLICE, D_, D_);
    wconv<<<dim3(D_/32,  D_/32),  thr>>>(W_ao,  wao, D_,  D_);
    wconv<<<dim3(FF_/32, D_/32),  thr>>>(W_i,   wi,  D_,  FF_);
    wconv<<<dim3(D_/32,  FF_/32), thr>>>(W_o,   wo,  FF_, D_);

    // tf32-rounded input copies
    rconv<<<(unsigned)((size_t)MW * D_ / 256), thr>>>(word, d_wordr);
    rconv<<<(unsigned)((size_t)ME * D_ / 256), thr>>>(ent,  d_entr);

    // packed projections, interleaved into [B,T,D]
    Dest4 dpW;
    dpW.d[0] = { d_q1, b_q   };
    dpW.d[1] = { d_q2, b_w2e };
    dpW.d[2] = { d_k,  b_k   };
    dpW.d[3] = { d_v,  b_v   };
    gemm_tc<<<dim3(4*D_/128, MW/128), thr, SMEM_DYN>>>(d_wordr, wpw,
        dpW, MW, 4*D_, D_, D_, S_, 0, 2);

    Dest4 dpE;
    dpE.d[0] = { d_q1, b_e2w };
    dpE.d[1] = { d_q2, b_e2e };
    dpE.d[2] = { d_k,  b_k   };
    dpE.d[3] = { d_v,  b_v   };
    gemm_tc<<<dim3(4*D_/128, ME/128), thr, SMEM_DYN>>>(d_entr, wpe,
        dpE, ME, 4*D_, D_, D_, E_, S_, 2);

    // V transpose for attention
    vtrans<<<dim3(T_/32, DH_/32, B_*H_), thr>>>(d_v, d_vt);

    // attention
    attn_tc<<<dim3(T_/128, H_, B_), thr, ATT_SMEM>>>(d_q1, d_q2, d_k, d_vt,
                                                     mask, d_ctx);

    // AO projection + LN (LN output tf32-rounded: feeds FFN1 + residual)
    Dest4 dpA;
    dpA.d[0] = { d_tmp, b_ao };
    dpA.d[1] = dpA.d[0]; dpA.d[2] = dpA.d[0]; dpA.d[3] = dpA.d[0];
    gemm_tc<<<dim3(D_/128, NT_/128), thr, SMEM_DYN>>>(d_ctx, wao,
        dpA, NT_, D_, D_, D_, NT_, 0, 0);
    ln_kernel<<<NT_, thr>>>(d_tmp, word, ent, d_ao, 0, gm_ao, bt_ao, d_ao, 0, 1);

    // FFN1 (+GELU, rounded out)
    Dest4 dpI;
    dpI.d[0] = { d_inter, b_i };
    dpI.d[1] = dpI.d[0]; dpI.d[2] = dpI.d[0]; dpI.d[3] = dpI.d[0];
    gemm_tc<<<dim3(FF_/128, NT_/128), thr, SMEM_DYN>>>(d_ao, wi,
        dpI, NT_, FF_, D_, FF_, NT_, 0, 1);

    // FFN2
    Dest4 dpO;
    dpO.d[0] = { d_tmp, b_o };
    dpO.d[1] = dpO.d[0]; dpO.d[2] = dpO.d[0]; dpO.d[3] = dpO.d[0];
    gemm_tc<<<dim3(D_/128, NT_/128), thr, SMEM_DYN>>>(d_inter, wo,
        dpO, NT_, D_, FF_, D_, NT_, 0, 0);

    // final LN -> split (word, entity) output, full precision
    ln_kernel<<<NT_, thr>>>(d_tmp, nullptr, nullptr, d_ao, 1, gm_o, bt_o,
                            (float*)d_out, 1, 0);
}

// round 8
// speedup vs baseline: 1.0992x; 1.0992x over previous
#include <cuda_runtime.h>
#include <cuda_bf16.h>
#include <stdint.h>
#include <math.h>

// Shapes (fixed for this problem)
#define B_  16
#define S_  512
#define E_  128
#define T_  640      // S_ + E_
#define D_  768
#define H_  12
#define DH_ 64
#define FF_ 3072
#define NT_ (B_*T_) // 10240

typedef __nv_bfloat16 bf16;
typedef unsigned int       u32;
typedef unsigned long long u64;

// ---------------- scratch (__device__ globals) ------------------------------
__device__ float g_ao [(size_t)NT_*D_];
__device__ float g_tmp[(size_t)NT_*D_];

__device__ bf16 g_word_h[(size_t)B_*S_*D_], g_word_l[(size_t)B_*S_*D_];
__device__ bf16 g_ent_h [(size_t)B_*E_*D_], g_ent_l [(size_t)B_*E_*D_];
__device__ bf16 g_q1h[(size_t)NT_*D_], g_q1l[(size_t)NT_*D_];
__device__ bf16 g_q2h[(size_t)NT_*D_], g_q2l[(size_t)NT_*D_];
__device__ bf16 g_kh [(size_t)NT_*D_], g_kl [(size_t)NT_*D_];
__device__ bf16 g_vh [(size_t)NT_*D_], g_vl [(size_t)NT_*D_];
__device__ bf16 g_ctx_h[(size_t)NT_*D_], g_ctx_l[(size_t)NT_*D_];
__device__ bf16 g_ao_h [(size_t)NT_*D_], g_ao_l [(size_t)NT_*D_];
__device__ bf16 g_int_h[(size_t)NT_*FF_], g_int_l[(size_t)NT_*FF_];

// packed split weights ([N,K] row-major)
__device__ bf16 g_wpw_h[4*D_*D_], g_wpw_l[4*D_*D_];   // word: q | w2e | k | v
__device__ bf16 g_wpe_h[4*D_*D_], g_wpe_l[4*D_*D_];   // ent:  e2w | e2e | k | v
__device__ bf16 g_wao_h[D_*D_],  g_wao_l[D_*D_];
__device__ bf16 g_wi_h [FF_*D_], g_wi_l [FF_*D_];
__device__ bf16 g_wo_h [D_*FF_], g_wo_l [D_*FF_];

struct DestPack { float* y; bf16* yh; bf16* yl; const float* bias; };
struct Dest4 { DestPack d[4]; };

// ---------------- PTX helpers ----------------------------------------------
__device__ __forceinline__ u32 smem_u32(const void* p) {
    u32 a;
    asm("{ .reg .u64 t; cvta.to.shared.u64 t, %1; cvt.u32.u64 %0, t; }" : "=r"(a) : "l"(p));
    return a;
}
__device__ __forceinline__ void cpa16(u32 s, const void* g) {
    asm volatile("cp.async.cg.shared.global [%0], [%1], 16;" :: "r"(s), "l"(g));
}
__device__ __forceinline__ void ldsm4(u32 addr, u32& r0, u32& r1, u32& r2, u32& r3) {
    asm volatile("ldmatrix.sync.aligned.m8n8.x4.shared.b16 {%0,%1,%2,%3}, [%4];"
                 : "=r"(r0), "=r"(r1), "=r"(r2), "=r"(r3) : "r"(addr));
}
__device__ __forceinline__ void ldsm4t(u32 addr, u32& r0, u32& r1, u32& r2, u32& r3) {
    asm volatile("ldmatrix.sync.aligned.m8n8.x4.trans.shared.b16 {%0,%1,%2,%3}, [%4];"
                 : "=r"(r0), "=r"(r1), "=r"(r2), "=r"(r3) : "r"(addr));
}
__device__ __forceinline__ void mma16816(float* c, const u32* a, u32 b0, u32 b1) {
    asm volatile(
        "mma.sync.aligned.m16n8k16.row.col.f32.bf16.bf16.f32 "
        "{%0,%1,%2,%3}, {%4,%5,%6,%7}, {%8,%9}, {%0,%1,%2,%3};"
        : "+f"(c[0]), "+f"(c[1]), "+f"(c[2]), "+f"(c[3])
        : "r"(a[0]), "r"(a[1]), "r"(a[2]), "r"(a[3]), "r"(b0), "r"(b1));
}
__device__ __forceinline__ float fexp(float x) {
    x = fmaxf(x, -80.f);
    float y = x * 1.4426950408889634f;
    int n = __float2int_rn(y);
    float f = y - (float)n;
    float p = 1.33336e-3f;
    p = fmaf(p, f, 9.61813e-3f);
    p = fmaf(p, f, 5.5504109e-2f);
    p = fmaf(p, f, 2.4022651e-1f);
    p = fmaf(p, f, 6.9314718e-1f);
    p = fmaf(p, f, 1.0f);
    return p * __int_as_float((n + 127) << 23);
}
__device__ __forceinline__ u32 pack_bf2(float a, float b) {
    __nv_bfloat162 t = __floats2bfloat162_rn(a, b);
    return *(u32*)&t;
}
__device__ __forceinline__ float bf_lo(float v) {
    return v - __bfloat162float(__float2bfloat16(v));
}

// ---------------- weight transpose + split ----------------------------------
__global__ __launch_bounds__(256)
void wconv(const float* __restrict__ W, bf16* __restrict__ th, bf16* __restrict__ tl,
           int K, int N)
{
    __shared__ float t[32][33];
    const int n0 = blockIdx.x * 32, k0 = blockIdx.y * 32;
    const int tx = threadIdx.x & 31, ty = threadIdx.x >> 5;
#pragma unroll
    for (int i = 0; i < 4; i++)
        t[ty + i*8][tx] = W[(size_t)(k0 + ty + i*8) * N + n0 + tx];
    __syncthreads();
#pragma unroll
    for (int i = 0; i < 4; i++) {
        float v = t[tx][ty + i*8];
        bf16 h = __float2bfloat16(v);
        size_t o = (size_t)(n0 + ty + i*8) * K + k0 + tx;
        th[o] = h;
        tl[o] = __float2bfloat16(v - __bfloat162float(h));
    }
}

// ---------------- activation split ------------------------------------------
__global__ __launch_bounds__(256)
void aconv(const float* __restrict__ x, bf16* __restrict__ h, bf16* __restrict__ l)
{
    size_t i = (size_t)blockIdx.x * 256 + threadIdx.x;
    float v = x[i];
    bf16 hi = __float2bfloat16(v);
    h[i] = hi;
    l[i] = __float2bfloat16(v - __bfloat162float(hi));
}

// ---------------- mma.sync split-bf16 GEMM (128x128 CTA, 32x64 warp) ---------
// Y[m,n] = A[m,:] @ Bt[n,:] + bias ; dest by n0 / nsplit; row remap seg/rowoff.
// act==0: fp32 out. act==1: GELU + split out. act==2: bias + split out.
#define BK_     32
#define TILE_BY (128*80)              // 10240 B per tile (80B padded rows)
#define STG_BY  (4*TILE_BY)           // 40960
#define SMEM_DYN (3*STG_BY)           // 122880

__global__ __launch_bounds__(256, 1)
void gemm_tc(const bf16* __restrict__ Ah, const bf16* __restrict__ Al,
             const bf16* __restrict__ Bh, const bf16* __restrict__ Bl,
             Dest4 dp, int M, int N, int K, int nsplit, int seg, int rowoff, int act)
{
    extern __shared__ char smem[];
    const u32 sb = smem_u32(smem);
    const int tid  = threadIdx.x;
    const int lane = tid & 31;
    const int wid  = tid >> 5;
    const int wm   = wid >> 1;
    const int wn   = wid & 1;
    const int n0 = blockIdx.x * 128;
    const int m0 = blockIdx.y * 128;
    const int nk = K / BK_;

    const bf16* srcs[4] = { Ah + (size_t)m0 * K, Al + (size_t)m0 * K,
                            Bh + (size_t)n0 * K, Bl + (size_t)n0 * K };

    auto load_chunk = [&](int s, int kc) {
        const int k0c = kc * BK_;
#pragma unroll
        for (int i = 0; i < 8; i++) {
            int c   = tid + i * 256;
            int t   = c >> 9;
            int cc  = c & 511;
            int r   = cc >> 2;
            int c16 = cc & 3;
            cpa16(sb + (u32)s * STG_BY + (u32)t * TILE_BY + (u32)(r * 80 + c16 * 16),
                  srcs[t] + k0c + (size_t)r * K + c16 * 8);
        }
        asm volatile("cp.async.commit_group;" ::: "memory");
    };

    float acc[2][8][4];
#pragma unroll
    for (int mt = 0; mt < 2; mt++)
#pragma unroll
        for (int nt = 0; nt < 8; nt++)
#pragma unroll
            for (int j = 0; j < 4; j++) acc[mt][nt][j] = 0.f;

    const u32 frag_row = (u32)(lane & 15);
    const u32 frag_col = (u32)((lane >> 4) << 4);

    load_chunk(0, 0);
    load_chunk(1, 1);

    for (int kc = 0; kc < nk; kc++) {
        const int s = kc % 3;
        if (kc + 2 < nk) {
            load_chunk((kc + 2) % 3, kc + 2);
            asm volatile("cp.async.wait_group 2;" ::: "memory");
        } else if (kc + 1 < nk) {
            asm volatile("cp.async.wait_group 1;" ::: "memory");
        } else {
            asm volatile("cp.async.wait_group 0;" ::: "memory");
        }
        __syncthreads();

        const u32 stg = sb + (u32)s * STG_BY;
        const u32 aBaseH = stg + 0 * TILE_BY;
        const u32 aBaseL = stg + 1 * TILE_BY;
        const u32 bBaseH = stg + 2 * TILE_BY;
        const u32 bBaseL = stg + 3 * TILE_BY;

#pragma unroll
        for (int ks = 0; ks < 2; ks++) {
            const u32 kByte = (u32)(ks * 32) + frag_col;
            u32 ah[2][4], al[2][4], bh[4][4], bl[4][4];
#pragma unroll
            for (int mt = 0; mt < 2; mt++) {
                u32 ro = (u32)(wm * 32 + mt * 16) + frag_row;
                ldsm4(aBaseH + ro * 80 + kByte, ah[mt][0], ah[mt][1], ah[mt][2], ah[mt][3]);
                ldsm4(aBaseL + ro * 80 + kByte, al[mt][0], al[mt][1], al[mt][2], al[mt][3]);
            }
#pragma unroll
            for (int np = 0; np < 4; np++) {
                u32 ro = (u32)(wn * 64 + np * 16) + frag_row;
                ldsm4(bBaseH + ro * 80 + kByte, bh[np][0], bh[np][1], bh[np][2], bh[np][3]);
                ldsm4(bBaseL + ro * 80 + kByte, bl[np][0], bl[np][1], bl[np][2], bl[np][3]);
            }
#pragma unroll
            for (int mt = 0; mt < 2; mt++)
#pragma unroll
                for (int nt = 0; nt < 8; nt++) {
                    int np = nt >> 1, sel = nt & 1;
                    u32 b0h = bh[np][sel], b1h = bh[np][sel + 2];
                    u32 b0l = bl[np][sel], b1l = bl[np][sel + 2];
                    mma16816(acc[mt][nt], ah[mt], b0h, b1h);
                    mma16816(acc[mt][nt], ah[mt], b0l, b1l);
                    mma16816(acc[mt][nt], al[mt], b0h, b1h);
                }
        }
        __syncthreads();
    }

    // epilogue: dest by n-block
    const int di = n0 / nsplit;
    float* Y  = dp.d[di].y;
    bf16* Yh  = dp.d[di].yh;
    bf16* Yl  = dp.d[di].yl;
    const float* bias = dp.d[di].bias;
    const int ncol_off = di * nsplit;

#pragma unroll
    for (int mt = 0; mt < 2; mt++) {
#pragma unroll
        for (int half = 0; half < 2; half++) {
            int mlog = m0 + wm * 32 + mt * 16 + (lane >> 2) + half * 8;
            size_t phys = (size_t)(mlog / seg) * T_ + (mlog % seg) + rowoff;
#pragma unroll
            for (int nt = 0; nt < 8; nt++) {
                int col = n0 + wn * 64 + nt * 8 + (lane & 3) * 2 - ncol_off;
                float v0 = acc[mt][nt][half * 2 + 0] + bias[col + 0];
                float v1 = acc[mt][nt][half * 2 + 1] + bias[col + 1];
                if (act == 0) {
                    *(float2*)(Y + phys * (size_t)nsplit + col) = make_float2(v0, v1);
                } else {
                    if (act == 1) {
                        v0 = 0.5f * v0 * (1.0f + erff(v0 * 0.70710678f));
                        v1 = 0.5f * v1 * (1.0f + erff(v1 * 0.70710678f));
                    }
                    *(u32*)(Yh + phys * (size_t)nsplit + col) = pack_bf2(v0, v1);
                    *(u32*)(Yl + phys * (size_t)nsplit + col) = pack_bf2(bf_lo(v0), bf_lo(v1));
                }
            }
        }
    }
}

// ---------------- tensor-core flash attention (R5, unchanged) ----------------
#define QT_BY   (128*144)
#define A_Q1H   0
#define A_Q1L   (1*QT_BY)
#define A_Q2H   (2*QT_BY)
#define A_Q2L   (3*QT_BY)
#define A_KH    (4*QT_BY)
#define A_KL    (5*QT_BY)
#define A_VH    (6*QT_BY)
#define A_VL    (7*QT_BY)
#define A_MS    (8*QT_BY)
#define ATT_SMEM (8*QT_BY + 512)

__global__ __launch_bounds__(256, 1)
void attn_tc(const bf16* __restrict__ q1h, const bf16* __restrict__ q1l,
             const bf16* __restrict__ q2h, const bf16* __restrict__ q2l,
             const bf16* __restrict__ kh,  const bf16* __restrict__ kl,
             const bf16* __restrict__ vh,  const bf16* __restrict__ vl,
             const float* __restrict__ mask,
             bf16* __restrict__ ctxH, bf16* __restrict__ ctxL)
{
    extern __shared__ char smem[];
    const u32 sb = smem_u32(smem);
    float* maskS = (float*)(smem + A_MS);

    const int b  = blockIdx.z;
    const int h  = blockIdx.y;
    const int q0 = blockIdx.x * 128;
    const int tid  = threadIdx.x;
    const int lane = tid & 31;
    const int w    = tid >> 5;

    const u32 frag_row = (u32)(lane & 15);
    const u32 frag_col = (u32)((lane >> 4) << 4);

    {
        const bf16* srcQ[4] = { q1h, q1l, q2h, q2l };
#pragma unroll
        for (int i = 0; i < 16; i++) {
            int idx = tid + i * 256;
            int arr = idx >> 10;
            int rr  = (idx >> 3) & 127;
            int ch  = idx & 7;
            cpa16(sb + (u32)(arr * QT_BY + rr * 144 + ch * 16),
                  srcQ[arr] + (size_t)(b * T_ + q0 + rr) * D_ + h * DH_ + ch * 8);
        }
        asm volatile("cp.async.commit_group;" ::: "memory");
    }

    float Oa[8][4];
#pragma unroll
    for (int od = 0; od < 8; od++)
#pragma unroll
        for (int j = 0; j < 4; j++) Oa[od][j] = 0.f;
    float m0 = -1e30f, m1 = -1e30f, l0 = 0.f, l1 = 0.f;

    for (int kt = 0; kt < 5; kt++) {
        __syncthreads();
        {
            const bf16* srcT[4] = { kh, kl, vh, vl };
#pragma unroll
            for (int i = 0; i < 16; i++) {
                int idx = tid + i * 256;
                int arr = idx >> 10;
                int rr  = (idx >> 3) & 127;
                int ch  = idx & 7;
                cpa16(sb + (u32)(A_KH + arr * QT_BY + rr * 144 + ch * 16),
                      srcT[arr] + (size_t)(b * T_ + kt * 128 + rr) * D_ + h * DH_ + ch * 8);
            }
            if (tid < 128) maskS[tid] = mask[b * T_ + kt * 128 + tid];
            asm volatile("cp.async.commit_group;" ::: "memory");
            asm volatile("cp.async.wait_group 0;" ::: "memory");
        }
        __syncthreads();

        const u32 qbh = sb + (u32)((kt < 4) ? A_Q1H : A_Q2H);
        const u32 qbl = qbh + QT_BY;

        float sc_[16][4];
#pragma unroll
        for (int nt = 0; nt < 16; nt++)
#pragma unroll
            for (int j = 0; j < 4; j++) sc_[nt][j] = 0.f;

#pragma unroll
        for (int ks = 0; ks < 4; ks++) {
            const u32 kByte = (u32)(ks * 32) + frag_col;
            u32 ah[4], al[4], bh[8][4], bl[8][4];
            u32 ro = (u32)(w * 16) + frag_row;
            ldsm4(qbh + ro * 144 + kByte, ah[0], ah[1], ah[2], ah[3]);
            ldsm4(qbl + ro * 144 + kByte, al[0], al[1], al[2], al[3]);
#pragma unroll
            for (int np = 0; np < 8; np++) {
                u32 kr = (u32)(np * 16) + frag_row;
                ldsm4(sb + A_KH + kr * 144 + kByte, bh[np][0], bh[np][1], bh[np][2], bh[np][3]);
                ldsm4(sb + A_KL + kr * 144 + kByte, bl[np][0], bl[np][1], bl[np][2], bl[np][3]);
            }
#pragma unroll
            for (int nt = 0; nt < 16; nt++) {
                int np = nt >> 1, sel = nt & 1;
                u32 b0h = bh[np][sel], b1h = bh[np][sel + 2];
                u32 b0l = bl[np][sel], b1l = bl[np][sel + 2];
                mma16816(sc_[nt], ah, b0h, b1h);
                mma16816(sc_[nt], ah, b0l, b1l);
                mma16816(sc_[nt], al, b0h, b1h);
            }
        }

        float rmax0 = -1e30f, rmax1 = -1e30f;
#pragma unroll
        for (int nt = 0; nt < 16; nt++) {
            int cbase = nt * 8 + (lane & 3) * 2;
            float mk0 = maskS[cbase], mk1 = maskS[cbase + 1];
            sc_[nt][0] = fmaf(sc_[nt][0], 0.125f, mk0);
            sc_[nt][1] = fmaf(sc_[nt][1], 0.125f, mk1);
            sc_[nt][2] = fmaf(sc_[nt][2], 0.125f, mk0);
            sc_[nt][3] = fmaf(sc_[nt][3], 0.125f, mk1);
            rmax0 = fmaxf(rmax0, fmaxf(sc_[nt][0], sc_[nt][1]));
            rmax1 = fmaxf(rmax1, fmaxf(sc_[nt][2], sc_[nt][3]));
        }
        rmax0 = fmaxf(rmax0, __shfl_xor_sync(0xffffffffu, rmax0, 1));
        rmax0 = fmaxf(rmax0, __shfl_xor_sync(0xffffffffu, rmax0, 2));
        rmax1 = fmaxf(rmax1, __shfl_xor_sync(0xffffffffu, rmax1, 1));
        rmax1 = fmaxf(rmax1, __shfl_xor_sync(0xffffffffu, rmax1, 2));

        float mn0 = fmaxf(m0, rmax0), mn1 = fmaxf(m1, rmax1);
        float f0 = fexp(m0 - mn0), f1 = fexp(m1 - mn1);
        float rs0 = 0.f, rs1 = 0.f;
#pragma unroll
        for (int nt = 0; nt < 16; nt++) {
            sc_[nt][0] = fexp(sc_[nt][0] - mn0);
            sc_[nt][1] = fexp(sc_[nt][1] - mn0);
            sc_[nt][2] = fexp(sc_[nt][2] - mn1);
            sc_[nt][3] = fexp(sc_[nt][3] - mn1);
            rs0 += sc_[nt][0] + sc_[nt][1];
            rs1 += sc_[nt][2] + sc_[nt][3];
        }
        rs0 += __shfl_xor_sync(0xffffffffu, rs0, 1);
        rs0 += __shfl_xor_sync(0xffffffffu, rs0, 2);
        rs1 += __shfl_xor_sync(0xffffffffu, rs1, 1);
        rs1 += __shfl_xor_sync(0xffffffffu, rs1, 2);
        l0 = l0 * f0 + rs0;
        l1 = l1 * f1 + rs1;
        m0 = mn0; m1 = mn1;
#pragma unroll
        for (int od = 0; od < 8; od++) {
            Oa[od][0] *= f0; Oa[od][1] *= f0;
            Oa[od][2] *= f1; Oa[od][3] *= f1;
        }

#pragma unroll
        for (int ks2 = 0; ks2 < 8; ks2++) {
            float p00 = sc_[2*ks2][0],   p01 = sc_[2*ks2][1];
            float p02 = sc_[2*ks2][2],   p03 = sc_[2*ks2][3];
            float p10 = sc_[2*ks2+1][0], p11 = sc_[2*ks2+1][1];
            float p12 = sc_[2*ks2+1][2], p13 = sc_[2*ks2+1][3];
            u32 aPh[4], aPl[4];
            aPh[0] = pack_bf2(p00, p01);
            aPh[1] = pack_bf2(p02, p03);
            aPh[2] = pack_bf2(p10, p11);
            aPh[3] = pack_bf2(p12, p13);
            aPl[0] = pack_bf2(bf_lo(p00), bf_lo(p01));
            aPl[1] = pack_bf2(bf_lo(p02), bf_lo(p03));
            aPl[2] = pack_bf2(bf_lo(p10), bf_lo(p11));
            aPl[3] = pack_bf2(bf_lo(p12), bf_lo(p13));

            const u32 vr = (u32)(ks2 * 16) + frag_row;
#pragma unroll
            for (int nd = 0; nd < 4; nd++) {
                const u32 cByte = (u32)(nd * 32) + frag_col;
                u32 vh0, vh1, vh2, vh3, vl0, vl1, vl2, vl3;
                ldsm4t(sb + A_VH + vr * 144 + cByte, vh0, vh1, vh2, vh3);
                ldsm4t(sb + A_VL + vr * 144 + cByte, vl0, vl1, vl2, vl3);
                int od0 = nd * 2, od1 = nd * 2 + 1;
                mma16816(Oa[od0], aPh, vh0, vh1);
                mma16816(Oa[od0], aPh, vl0, vl1);
                mma16816(Oa[od0], aPl, vh0, vh1);
                mma16816(Oa[od1], aPh, vh2, vh3);
                mma16816(Oa[od1], aPh, vl2, vl3);
                mma16816(Oa[od1], aPl, vh2, vh3);
            }
        }
    }

    float inv0 = 1.f / l0, inv1 = 1.f / l1;
    int qa = q0 + w * 16 + (lane >> 2);
    int qb = qa + 8;
    size_t baseA = (size_t)(b * T_ + qa) * D_ + h * DH_;
    size_t baseB = (size_t)(b * T_ + qb) * D_ + h * DH_;
#pragma unroll
    for (int od = 0; od < 8; od++) {
        int col = od * 8 + (lane & 3) * 2;
        float o0 = Oa[od][0] * inv0, o1 = Oa[od][1] * inv0;
        float o2 = Oa[od][2] * inv1, o3 = Oa[od][3] * inv1;
        *(u32*)(ctxH + baseA + col) = pack_bf2(o0, o1);
        *(u32*)(ctxL + baseA + col) = pack_bf2(bf_lo(o0), bf_lo(o1));
        *(u32*)(ctxH + baseB + col) = pack_bf2(o2, o3);
        *(u32*)(ctxL + baseB + col) = pack_bf2(bf_lo(o2), bf_lo(o3));
    }
}

// ---------------- residual + LayerNorm ---------------------------------------
__global__ __launch_bounds__(256)
void ln_kernel(const float* __restrict__ raw,
               const float* __restrict__ rw, const float* __restrict__ re,
               const float* __restrict__ rfull, int use_full,
               const float* __restrict__ gm, const float* __restrict__ bt,
               float* __restrict__ out, int final_mode,
               bf16* __restrict__ outH, bf16* __restrict__ outL)
{
    const int row = blockIdx.x;
    const int b = row / T_, t = row % T_;
    const float* rp = use_full
        ? rfull + (size_t)row * D_
        : (t < S_ ? rw + ((size_t)(b * S_ + t)) * D_
                  : re + ((size_t)(b * E_ + t - S_)) * D_);
    const float* x = raw + (size_t)row * D_;

    float vv[3];
    float s = 0.f, sq = 0.f;
#pragma unroll
    for (int i = 0; i < 3; i++) {
        int c = threadIdx.x + i * 256;
        float val = x[c] + rp[c];
        vv[i] = val;
        s += val;
        sq += val * val;
    }
    const int lane = threadIdx.x & 31, w = threadIdx.x >> 5;
#pragma unroll
    for (int o = 16; o; o >>= 1) {
        s  += __shfl_xor_sync(0xffffffffu, s,  o);
        sq += __shfl_xor_sync(0xffffffffu, sq, o);
    }
    __shared__ float ws[8], wq[8];
    __shared__ float sm, sv;
    if (lane == 0) { ws[w] = s; wq[w] = sq; }
    __syncthreads();
    if (threadIdx.x == 0) {
        float ts = 0.f, tq = 0.f;
#pragma unroll
        for (int i = 0; i < 8; i++) { ts += ws[i]; tq += wq[i]; }
        float mean = ts * (1.f / D_);
        sm = mean;
        sv = rsqrtf(tq * (1.f / D_) - mean * mean + 1e-12f);
    }
    __syncthreads();
    const float mean = sm, inv = sv;

    float* o = final_mode
        ? (t < S_ ? out + ((size_t)(b * S_ + t)) * D_
                  : out + (size_t)B_ * S_ * D_ + ((size_t)(b * E_ + t - S_)) * D_)
        : out + (size_t)row * D_;
#pragma unroll
    for (int i = 0; i < 3; i++) {
        int c = threadIdx.x + i * 256;
        float y = (vv[i] - mean) * inv * gm[c] + bt[c];
        o[c] = y;
        if (outH) {
            bf16 h = __float2bfloat16(y);
            outH[(size_t)row * D_ + c] = h;
            outL[(size_t)row * D_ + c] = __float2bfloat16(y - __bfloat162float(h));
        }
    }
}

// ---------------- host -------------------------------------------------------
extern "C" void kernel_launch(void* const* d_in, const int* in_sizes, int n_in,
                              void* d_out, int out_size)
{
    const float* word  = (const float*)d_in[0];
    const float* ent   = (const float*)d_in[1];
    const float* mask  = (const float*)d_in[2];
    const float* W_q   = (const float*)d_in[3],  *b_q    = (const float*)d_in[4];
    const float* W_k   = (const float*)d_in[5],  *b_k    = (const float*)d_in[6];
    const float* W_v   = (const float*)d_in[7],  *b_v    = (const float*)d_in[8];
    const float* W_w2e = (const float*)d_in[9],  *b_w2e  = (const float*)d_in[10];
    const float* W_e2w = (const float*)d_in[11], *b_e2w  = (const float*)d_in[12];
    const float* W_e2e = (const float*)d_in[13], *b_e2e  = (const float*)d_in[14];
    const float* W_ao  = (const float*)d_in[15], *b_ao   = (const float*)d_in[16];
    const float* gm_ao = (const float*)d_in[17], *bt_ao  = (const float*)d_in[18];
    const float* W_i   = (const float*)d_in[19], *b_i    = (const float*)d_in[20];
    const float* W_o   = (const float*)d_in[21], *b_o    = (const float*)d_in[22];
    const float* gm_o  = (const float*)d_in[23], *bt_o   = (const float*)d_in[24];

    void* p;
    cudaGetSymbolAddress(&p, g_ao);    float* d_ao  = (float*)p;
    cudaGetSymbolAddress(&p, g_tmp);   float* d_tmp = (float*)p;

    bf16 *wordH,*wordL,*entH,*entL,*q1H,*q1L,*q2H,*q2L,*kH,*kL,*vH,*vL,*ctxH,*ctxL,*aoH,*aoL,*intH,*intL;
    cudaGetSymbolAddress(&p, g_word_h); wordH = (bf16*)p;
    cudaGetSymbolAddress(&p, g_word_l); wordL = (bf16*)p;
    cudaGetSymbolAddress(&p, g_ent_h);  entH  = (bf16*)p;
    cudaGetSymbolAddress(&p, g_ent_l);  entL  = (bf16*)p;
    cudaGetSymbolAddress(&p, g_q1h);    q1H   = (bf16*)p;
    cudaGetSymbolAddress(&p, g_q1l);    q1L   = (bf16*)p;
    cudaGetSymbolAddress(&p, g_q2h);    q2H   = (bf16*)p;
    cudaGetSymbolAddress(&p, g_q2l);    q2L   = (bf16*)p;
    cudaGetSymbolAddress(&p, g_kh);     kH    = (bf16*)p;
    cudaGetSymbolAddress(&p, g_kl);     kL    = (bf16*)p;
    cudaGetSymbolAddress(&p, g_vh);     vH    = (bf16*)p;
    cudaGetSymbolAddress(&p, g_vl);     vL    = (bf16*)p;
    cudaGetSymbolAddress(&p, g_ctx_h);  ctxH  = (bf16*)p;
    cudaGetSymbolAddress(&p, g_ctx_l);  ctxL  = (bf16*)p;
    cudaGetSymbolAddress(&p, g_ao_h);   aoH   = (bf16*)p;
    cudaGetSymbolAddress(&p, g_ao_l);   aoL   = (bf16*)p;
    cudaGetSymbolAddress(&p, g_int_h);  intH  = (bf16*)p;
    cudaGetSymbolAddress(&p, g_int_l);  intL  = (bf16*)p;

    bf16 *wpwH,*wpwL,*wpeH,*wpeL,*waoH,*waoL,*wiH,*wiL,*woH,*woL;
    cudaGetSymbolAddress(&p, g_wpw_h); wpwH = (bf16*)p;
    cudaGetSymbolAddress(&p, g_wpw_l); wpwL = (bf16*)p;
    cudaGetSymbolAddress(&p, g_wpe_h); wpeH = (bf16*)p;
    cudaGetSymbolAddress(&p, g_wpe_l); wpeL = (bf16*)p;
    cudaGetSymbolAddress(&p, g_wao_h); waoH = (bf16*)p;
    cudaGetSymbolAddress(&p, g_wao_l); waoL = (bf16*)p;
    cudaGetSymbolAddress(&p, g_wi_h);  wiH  = (bf16*)p;
    cudaGetSymbolAddress(&p, g_wi_l);  wiL  = (bf16*)p;
    cudaGetSymbolAddress(&p, g_wo_h);  woH  = (bf16*)p;
    cudaGetSymbolAddress(&p, g_wo_l);  woL  = (bf16*)p;

    cudaFuncSetAttribute(gemm_tc, cudaFuncAttributeMaxDynamicSharedMemorySize, SMEM_DYN);
    cudaFuncSetAttribute(attn_tc, cudaFuncAttributeMaxDynamicSharedMemorySize, ATT_SMEM);

    const dim3 thr(256);
    const int MW = B_ * S_;
    const int ME = B_ * E_;
    const size_t WSLICE = (size_t)D_ * D_;

    // weight transpose+split into packed buffers
    wconv<<<dim3(D_/32,  D_/32),  thr>>>(W_q,   wpwH + 0*WSLICE, wpwL + 0*WSLICE, D_, D_);
    wconv<<<dim3(D_/32,  D_/32),  thr>>>(W_w2e, wpwH + 1*WSLICE, wpwL + 1*WSLICE, D_, D_);
    wconv<<<dim3(D_/32,  D_/32),  thr>>>(W_k,   wpwH + 2*WSLICE, wpwL + 2*WSLICE, D_, D_);
    wconv<<<dim3(D_/32,  D_/32),  thr>>>(W_v,   wpwH + 3*WSLICE, wpwL + 3*WSLICE, D_, D_);
    wconv<<<dim3(D_/32,  D_/32),  thr>>>(W_e2w, wpeH + 0*WSLICE, wpeL + 0*WSLICE, D_, D_);
    wconv<<<dim3(D_/32,  D_/32),  thr>>>(W_e2e, wpeH + 1*WSLICE, wpeL + 1*WSLICE, D_, D_);
    wconv<<<dim3(D_/32,  D_/32),  thr>>>(W_k,   wpeH + 2*WSLICE, wpeL + 2*WSLICE, D_, D_);
    wconv<<<dim3(D_/32,  D_/32),  thr>>>(W_v,   wpeH + 3*WSLICE, wpeL + 3*WSLICE, D_, D_);
    wconv<<<dim3(D_/32,  D_/32),  thr>>>(W_ao,  waoH, waoL, D_,  D_);
    wconv<<<dim3(FF_/32, D_/32),  thr>>>(W_i,   wiH,  wiL,  D_,  FF_);
    wconv<<<dim3(D_/32,  FF_/32), thr>>>(W_o,   woH,  woL,  FF_, D_);

    aconv<<<(unsigned)((size_t)MW * D_ / 256), thr>>>(word, wordH, wordL);
    aconv<<<(unsigned)((size_t)ME * D_ / 256), thr>>>(ent,  entH,  entL);

    // packed projections (word + entity), interleaved into [B,T,D]
    Dest4 dpW;
    dpW.d[0] = { nullptr, q1H, q1L, b_q   };
    dpW.d[1] = { nullptr, q2H, q2L, b_w2e };
    dpW.d[2] = { nullptr, kH,  kL,  b_k   };
    dpW.d[3] = { nullptr, vH,  vL,  b_v   };
    gemm_tc<<<dim3(4*D_/128, MW/128), thr, SMEM_DYN>>>(wordH, wordL, wpwH, wpwL,
        dpW, MW, 4*D_, D_, D_, S_, 0, 2);

    Dest4 dpE;
    dpE.d[0] = { nullptr, q1H, q1L, b_e2w };
    dpE.d[1] = { nullptr, q2H, q2L, b_e2e };
    dpE.d[2] = { nullptr, kH,  kL,  b_k   };
    dpE.d[3] = { nullptr, vH,  vL,  b_v   };
    gemm_tc<<<dim3(4*D_/128, ME/128), thr, SMEM_DYN>>>(entH, entL, wpeH, wpeL,
        dpE, ME, 4*D_, D_, D_, E_, S_, 2);

    // attention -> split ctx
    attn_tc<<<dim3(T_/128, H_, B_), thr, ATT_SMEM>>>(q1H, q1L, q2H, q2L, kH, kL, vH, vL,
                                                     mask, ctxH, ctxL);

    // AO projection + LN
    Dest4 dpA;
    dpA.d[0] = { d_tmp, nullptr, nullptr, b_ao };
    dpA.d[1] = dpA.d[0]; dpA.d[2] = dpA.d[0]; dpA.d[3] = dpA.d[0];
    gemm_tc<<<dim3(D_/128, NT_/128), thr, SMEM_DYN>>>(ctxH, ctxL, waoH, waoL,
        dpA, NT_, D_, D_, D_, NT_, 0, 0);
    ln_kernel<<<NT_, thr>>>(d_tmp, word, ent, d_ao, 0, gm_ao, bt_ao, d_ao, 0, aoH, aoL);

    // FFN1 (+GELU, split out)
    Dest4 dpI;
    dpI.d[0] = { nullptr, intH, intL, b_i };
    dpI.d[1] = dpI.d[0]; dpI.d[2] = dpI.d[0]; dpI.d[3] = dpI.d[0];
    gemm_tc<<<dim3(FF_/128, NT_/128), thr, SMEM_DYN>>>(aoH, aoL, wiH, wiL,
        dpI, NT_, FF_, D_, FF_, NT_, 0, 1);

    // FFN2
    Dest4 dpO;
    dpO.d[0] = { d_tmp, nullptr, nullptr, b_o };
    dpO.d[1] = dpO.d[0]; dpO.d[2] = dpO.d[0]; dpO.d[3] = dpO.d[0];
    gemm_tc<<<dim3(D_/128, NT_/128), thr, SMEM_DYN>>>(intH, intL, woH, woL,
        dpO, NT_, D_, FF_, D_, NT_, 0, 0);

    // final LN -> split (word, entity) output
    ln_kernel<<<NT_, thr>>>(d_tmp, nullptr, nullptr, d_ao, 1, gm_o, bt_o,
                            (float*)d_out, 1, nullptr, nullptr);
}

// round 9
// speedup vs baseline: 1.7121x; 1.5576x over previous
#include <cuda_runtime.h>
#include <cuda_fp16.h>
#include <stdint.h>
#include <math.h>

// Shapes (fixed for this problem)
#define B_  16
#define S_  512
#define E_  128
#define T_  640      // S_ + E_
#define D_  768
#define H_  12
#define DH_ 64
#define FF_ 3072
#define NT_ (B_*T_) // 10240

typedef unsigned int       u32;
typedef unsigned long long u64;

// ---------------- scratch (__device__ globals) ------------------------------
__device__ float g_ao [(size_t)NT_*D_];
__device__ float g_tmp[(size_t)NT_*D_];

// fp16 split activations (A-side: hi+lo; B-side K/V: single)
__device__ half g_word_h[(size_t)B_*S_*D_], g_word_l[(size_t)B_*S_*D_];
__device__ half g_ent_h [(size_t)B_*E_*D_], g_ent_l [(size_t)B_*E_*D_];
__device__ half g_q1h[(size_t)NT_*D_], g_q1l[(size_t)NT_*D_];
__device__ half g_q2h[(size_t)NT_*D_], g_q2l[(size_t)NT_*D_];
__device__ half g_kh [(size_t)NT_*D_];
__device__ half g_vh [(size_t)NT_*D_];
__device__ half g_ctx_h[(size_t)NT_*D_], g_ctx_l[(size_t)NT_*D_];
__device__ half g_ao_h [(size_t)NT_*D_], g_ao_l [(size_t)NT_*D_];
__device__ half g_int_h[(size_t)NT_*FF_], g_int_l[(size_t)NT_*FF_];

// packed fp16 weights ([N,K] row-major, single precision level)
__device__ half g_wpw[4*D_*D_];   // word: q | w2e | k | v
__device__ half g_wpe[4*D_*D_];   // ent:  e2w | e2e | k | v
__device__ half g_wao[D_*D_];
__device__ half g_wi [FF_*D_];
__device__ half g_wo [D_*FF_];

struct DestPack { float* y; half* yh; half* yl; const float* bias; };
struct Dest4 { DestPack d[4]; };

// ---------------- PTX helpers ----------------------------------------------
__device__ __forceinline__ u32 smem_u32(const void* p) {
    u32 a;
    asm("{ .reg .u64 t; cvta.to.shared.u64 t, %1; cvt.u32.u64 %0, t; }" : "=r"(a) : "l"(p));
    return a;
}
__device__ __forceinline__ void cpa16(u32 s, const void* g) {
    asm volatile("cp.async.cg.shared.global [%0], [%1], 16;" :: "r"(s), "l"(g));
}
__device__ __forceinline__ void ldsm4(u32 addr, u32& r0, u32& r1, u32& r2, u32& r3) {
    asm volatile("ldmatrix.sync.aligned.m8n8.x4.shared.b16 {%0,%1,%2,%3}, [%4];"
                 : "=r"(r0), "=r"(r1), "=r"(r2), "=r"(r3) : "r"(addr));
}
__device__ __forceinline__ void ldsm4t(u32 addr, u32& r0, u32& r1, u32& r2, u32& r3) {
    asm volatile("ldmatrix.sync.aligned.m8n8.x4.trans.shared.b16 {%0,%1,%2,%3}, [%4];"
                 : "=r"(r0), "=r"(r1), "=r"(r2), "=r"(r3) : "r"(addr));
}
__device__ __forceinline__ void mma_f16(float* c, const u32* a, u32 b0, u32 b1) {
    asm volatile(
        "mma.sync.aligned.m16n8k16.row.col.f32.f16.f16.f32 "
        "{%0,%1,%2,%3}, {%4,%5,%6,%7}, {%8,%9}, {%0,%1,%2,%3};"
        : "+f"(c[0]), "+f"(c[1]), "+f"(c[2]), "+f"(c[3])
        : "r"(a[0]), "r"(a[1]), "r"(a[2]), "r"(a[3]), "r"(b0), "r"(b1));
}
__device__ __forceinline__ float fexp(float x) {
    x = fmaxf(x, -80.f);
    float y = x * 1.4426950408889634f;
    int n = __float2int_rn(y);
    float f = y - (float)n;
    float p = 1.33336e-3f;
    p = fmaf(p, f, 9.61813e-3f);
    p = fmaf(p, f, 5.5504109e-2f);
    p = fmaf(p, f, 2.4022651e-1f);
    p = fmaf(p, f, 6.9314718e-1f);
    p = fmaf(p, f, 1.0f);
    return p * __int_as_float((n + 127) << 23);
}
__device__ __forceinline__ u32 pack_h2(float a, float b) {
    __half2 t = __floats2half2_rn(a, b);
    return *(u32*)&t;
}
__device__ __forceinline__ float h_lo(float v) {
    return v - __half2float(__float2half_rn(v));
}

// ---------------- weight transpose -> fp16 -----------------------------------
__global__ __launch_bounds__(256)
void wconv(const float* __restrict__ W, half* __restrict__ Wt, int K, int N)
{
    __shared__ float t[32][33];
    const int n0 = blockIdx.x * 32, k0 = blockIdx.y * 32;
    const int tx = threadIdx.x & 31, ty = threadIdx.x >> 5;
#pragma unroll
    for (int i = 0; i < 4; i++)
        t[ty + i*8][tx] = W[(size_t)(k0 + ty + i*8) * N + n0 + tx];
    __syncthreads();
#pragma unroll
    for (int i = 0; i < 4; i++)
        Wt[(size_t)(n0 + ty + i*8) * K + k0 + tx] = __float2half_rn(t[tx][ty + i*8]);
}

// ---------------- activation split (fp16 hi/lo) ------------------------------
__global__ __launch_bounds__(256)
void aconv(const float* __restrict__ x, half* __restrict__ h, half* __restrict__ l)
{
    size_t i = (size_t)blockIdx.x * 256 + threadIdx.x;
    float v = x[i];
    half hi = __float2half_rn(v);
    h[i] = hi;
    l[i] = __float2half_rn(v - __half2float(hi));
}

// ---------------- fp16 asymmetric-split GEMM (128x128 CTA, 32x64 warp) -------
// Y = (Ah+Al)[m,:] @ Bt[n,:] + bias ; dest by n0/nsplit; row remap seg/rowoff.
// act==0: fp32 out. act==1: GELU + h/l out. act==2: bias + h/l out (lo if yl).
#define BK_     32
#define TILE_BY (128*80)              // 10240 B per tile (80B padded rows)
#define STG_BY  (3*TILE_BY)           // 30720 (Ah, Al, B)
#define SMEM_DYN (3*STG_BY)           // 92160

__global__ __launch_bounds__(256, 1)
void gemm_tc(const half* __restrict__ Ah, const half* __restrict__ Al,
             const half* __restrict__ Bt,
             Dest4 dp, int M, int N, int K, int nsplit, int seg, int rowoff, int act)
{
    extern __shared__ char smem[];
    const u32 sb = smem_u32(smem);
    const int tid  = threadIdx.x;
    const int lane = tid & 31;
    const int wid  = tid >> 5;
    const int wm   = wid >> 1;
    const int wn   = wid & 1;
    const int n0 = blockIdx.x * 128;
    const int m0 = blockIdx.y * 128;
    const int nk = K / BK_;

    const half* srcs[3] = { Ah + (size_t)m0 * K, Al + (size_t)m0 * K,
                            Bt + (size_t)n0 * K };

    auto load_chunk = [&](int s, int kc) {
        const int k0c = kc * BK_;
#pragma unroll
        for (int i = 0; i < 6; i++) {
            int c   = tid + i * 256;      // 0..1535
            int t   = c >> 9;             // 0..2
            int cc  = c & 511;
            int r   = cc >> 2;
            int c16 = cc & 3;
            cpa16(sb + (u32)s * STG_BY + (u32)t * TILE_BY + (u32)(r * 80 + c16 * 16),
                  srcs[t] + k0c + (size_t)r * K + c16 * 8);
        }
        asm volatile("cp.async.commit_group;" ::: "memory");
    };

    float acc[2][8][4];
#pragma unroll
    for (int mt = 0; mt < 2; mt++)
#pragma unroll
        for (int nt = 0; nt < 8; nt++)
#pragma unroll
            for (int j = 0; j < 4; j++) acc[mt][nt][j] = 0.f;

    const u32 frag_row = (u32)(lane & 15);
    const u32 frag_col = (u32)((lane >> 4) << 4);

    load_chunk(0, 0);
    load_chunk(1, 1);

    for (int kc = 0; kc < nk; kc++) {
        const int s = kc % 3;
        if (kc + 2 < nk) {
            load_chunk((kc + 2) % 3, kc + 2);
            asm volatile("cp.async.wait_group 2;" ::: "memory");
        } else if (kc + 1 < nk) {
            asm volatile("cp.async.wait_group 1;" ::: "memory");
        } else {
            asm volatile("cp.async.wait_group 0;" ::: "memory");
        }
        __syncthreads();

        const u32 stg = sb + (u32)s * STG_BY;
        const u32 aBaseH = stg + 0 * TILE_BY;
        const u32 aBaseL = stg + 1 * TILE_BY;
        const u32 bBase  = stg + 2 * TILE_BY;

#pragma unroll
        for (int ks = 0; ks < 2; ks++) {
            const u32 kByte = (u32)(ks * 32) + frag_col;
            u32 ah[2][4], al[2][4], bb[4][4];
#pragma unroll
            for (int mt = 0; mt < 2; mt++) {
                u32 ro = (u32)(wm * 32 + mt * 16) + frag_row;
                ldsm4(aBaseH + ro * 80 + kByte, ah[mt][0], ah[mt][1], ah[mt][2], ah[mt][3]);
                ldsm4(aBaseL + ro * 80 + kByte, al[mt][0], al[mt][1], al[mt][2], al[mt][3]);
            }
#pragma unroll
            for (int np = 0; np < 4; np++) {
                u32 ro = (u32)(wn * 64 + np * 16) + frag_row;
                ldsm4(bBase + ro * 80 + kByte, bb[np][0], bb[np][1], bb[np][2], bb[np][3]);
            }
#pragma unroll
            for (int mt = 0; mt < 2; mt++)
#pragma unroll
                for (int nt = 0; nt < 8; nt++) {
                    int np = nt >> 1, sel = nt & 1;
                    u32 b0 = bb[np][sel], b1 = bb[np][sel + 2];
                    mma_f16(acc[mt][nt], ah[mt], b0, b1);
                    mma_f16(acc[mt][nt], al[mt], b0, b1);
                }
        }
        __syncthreads();
    }

    // epilogue: dest by n-block
    const int di = n0 / nsplit;
    float* Y  = dp.d[di].y;
    half* Yh  = dp.d[di].yh;
    half* Yl  = dp.d[di].yl;
    const float* bias = dp.d[di].bias;
    const int ncol_off = di * nsplit;

#pragma unroll
    for (int mt = 0; mt < 2; mt++) {
#pragma unroll
        for (int half_ = 0; half_ < 2; half_++) {
            int mlog = m0 + wm * 32 + mt * 16 + (lane >> 2) + half_ * 8;
            size_t phys = (size_t)(mlog / seg) * T_ + (mlog % seg) + rowoff;
#pragma unroll
            for (int nt = 0; nt < 8; nt++) {
                int col = n0 + wn * 64 + nt * 8 + (lane & 3) * 2 - ncol_off;
                float v0 = acc[mt][nt][half_ * 2 + 0] + bias[col + 0];
                float v1 = acc[mt][nt][half_ * 2 + 1] + bias[col + 1];
                if (act == 0) {
                    *(float2*)(Y + phys * (size_t)nsplit + col) = make_float2(v0, v1);
                } else {
                    if (act == 1) {
                        v0 = 0.5f * v0 * (1.0f + erff(v0 * 0.70710678f));
                        v1 = 0.5f * v1 * (1.0f + erff(v1 * 0.70710678f));
                    }
                    *(u32*)(Yh + phys * (size_t)nsplit + col) = pack_h2(v0, v1);
                    if (Yl)
                        *(u32*)(Yl + phys * (size_t)nsplit + col) = pack_h2(h_lo(v0), h_lo(v1));
                }
            }
        }
    }
}

// ---------------- fp16 flash attention ---------------------------------------
// Q split hi/lo (A side); K, V single fp16 (B side). 6 tiles of 128x144B.
#define QT_BY   (128*144)
#define A_Q1H   0
#define A_Q1L   (1*QT_BY)
#define A_Q2H   (2*QT_BY)
#define A_Q2L   (3*QT_BY)
#define A_K     (4*QT_BY)
#define A_V     (5*QT_BY)
#define A_MS    (6*QT_BY)
#define ATT_SMEM (6*QT_BY + 512)     // 111104

__global__ __launch_bounds__(256, 1)
void attn_tc(const half* __restrict__ q1h, const half* __restrict__ q1l,
             const half* __restrict__ q2h, const half* __restrict__ q2l,
             const half* __restrict__ kh,  const half* __restrict__ vh,
             const float* __restrict__ mask,
             half* __restrict__ ctxH, half* __restrict__ ctxL)
{
    extern __shared__ char smem[];
    const u32 sb = smem_u32(smem);
    float* maskS = (float*)(smem + A_MS);

    const int b  = blockIdx.z;
    const int h  = blockIdx.y;
    const int q0 = blockIdx.x * 128;
    const int tid  = threadIdx.x;
    const int lane = tid & 31;
    const int w    = tid >> 5;

    const u32 frag_row = (u32)(lane & 15);
    const u32 frag_col = (u32)((lane >> 4) << 4);

    {
        const half* srcQ[4] = { q1h, q1l, q2h, q2l };
#pragma unroll
        for (int i = 0; i < 16; i++) {
            int idx = tid + i * 256;
            int arr = idx >> 10;
            int rr  = (idx >> 3) & 127;
            int ch  = idx & 7;
            cpa16(sb + (u32)(arr * QT_BY + rr * 144 + ch * 16),
                  srcQ[arr] + (size_t)(b * T_ + q0 + rr) * D_ + h * DH_ + ch * 8);
        }
        asm volatile("cp.async.commit_group;" ::: "memory");
    }

    float Oa[8][4];
#pragma unroll
    for (int od = 0; od < 8; od++)
#pragma unroll
        for (int j = 0; j < 4; j++) Oa[od][j] = 0.f;
    float m0 = -1e30f, m1 = -1e30f, l0 = 0.f, l1 = 0.f;

    for (int kt = 0; kt < 5; kt++) {
        __syncthreads();
        {
            const half* srcT[2] = { kh, vh };
#pragma unroll
            for (int i = 0; i < 8; i++) {
                int idx = tid + i * 256;        // 0..2047
                int arr = idx >> 10;
                int rr  = (idx >> 3) & 127;
                int ch  = idx & 7;
                cpa16(sb + (u32)(A_K + arr * QT_BY + rr * 144 + ch * 16),
                      srcT[arr] + (size_t)(b * T_ + kt * 128 + rr) * D_ + h * DH_ + ch * 8);
            }
            if (tid < 128) maskS[tid] = mask[b * T_ + kt * 128 + tid];
            asm volatile("cp.async.commit_group;" ::: "memory");
            asm volatile("cp.async.wait_group 0;" ::: "memory");
        }
        __syncthreads();

        const u32 qbh = sb + (u32)((kt < 4) ? A_Q1H : A_Q2H);
        const u32 qbl = qbh + QT_BY;

        float sc_[16][4];
#pragma unroll
        for (int nt = 0; nt < 16; nt++)
#pragma unroll
            for (int j = 0; j < 4; j++) sc_[nt][j] = 0.f;

#pragma unroll
        for (int ks = 0; ks < 4; ks++) {
            const u32 kByte = (u32)(ks * 32) + frag_col;
            u32 ah[4], al[4], bh[8][4];
            u32 ro = (u32)(w * 16) + frag_row;
            ldsm4(qbh + ro * 144 + kByte, ah[0], ah[1], ah[2], ah[3]);
            ldsm4(qbl + ro * 144 + kByte, al[0], al[1], al[2], al[3]);
#pragma unroll
            for (int np = 0; np < 8; np++) {
                u32 kr = (u32)(np * 16) + frag_row;
                ldsm4(sb + A_K + kr * 144 + kByte, bh[np][0], bh[np][1], bh[np][2], bh[np][3]);
            }
#pragma unroll
            for (int nt = 0; nt < 16; nt++) {
                int np = nt >> 1, sel = nt & 1;
                u32 b0 = bh[np][sel], b1 = bh[np][sel + 2];
                mma_f16(sc_[nt], ah, b0, b1);
                mma_f16(sc_[nt], al, b0, b1);
            }
        }

        float rmax0 = -1e30f, rmax1 = -1e30f;
#pragma unroll
        for (int nt = 0; nt < 16; nt++) {
            int cbase = nt * 8 + (lane & 3) * 2;
            float mk0 = maskS[cbase], mk1 = maskS[cbase + 1];
            sc_[nt][0] = fmaf(sc_[nt][0], 0.125f, mk0);
            sc_[nt][1] = fmaf(sc_[nt][1], 0.125f, mk1);
            sc_[nt][2] = fmaf(sc_[nt][2], 0.125f, mk0);
            sc_[nt][3] = fmaf(sc_[nt][3], 0.125f, mk1);
            rmax0 = fmaxf(rmax0, fmaxf(sc_[nt][0], sc_[nt][1]));
            rmax1 = fmaxf(rmax1, fmaxf(sc_[nt][2], sc_[nt][3]));
        }
        rmax0 = fmaxf(rmax0, __shfl_xor_sync(0xffffffffu, rmax0, 1));
        rmax0 = fmaxf(rmax0, __shfl_xor_sync(0xffffffffu, rmax0, 2));
        rmax1 = fmaxf(rmax1, __shfl_xor_sync(0xffffffffu, rmax1, 1));
        rmax1 = fmaxf(rmax1, __shfl_xor_sync(0xffffffffu, rmax1, 2));

        float mn0 = fmaxf(m0, rmax0), mn1 = fmaxf(m1, rmax1);
        float f0 = fexp(m0 - mn0), f1 = fexp(m1 - mn1);
        float rs0 = 0.f, rs1 = 0.f;
#pragma unroll
        for (int nt = 0; nt < 16; nt++) {
            sc_[nt][0] = fexp(sc_[nt][0] - mn0);
            sc_[nt][1] = fexp(sc_[nt][1] - mn0);
            sc_[nt][2] = fexp(sc_[nt][2] - mn1);
            sc_[nt][3] = fexp(sc_[nt][3] - mn1);
            rs0 += sc_[nt][0] + sc_[nt][1];
            rs1 += sc_[nt][2] + sc_[nt][3];
        }
        rs0 += __shfl_xor_sync(0xffffffffu, rs0, 1);
        rs0 += __shfl_xor_sync(0xffffffffu, rs0, 2);
        rs1 += __shfl_xor_sync(0xffffffffu, rs1, 1);
        rs1 += __shfl_xor_sync(0xffffffffu, rs1, 2);
        l0 = l0 * f0 + rs0;
        l1 = l1 * f1 + rs1;
        m0 = mn0; m1 = mn1;
#pragma unroll
        for (int od = 0; od < 8; od++) {
            Oa[od][0] *= f0; Oa[od][1] *= f0;
            Oa[od][2] *= f1; Oa[od][3] *= f1;
        }

        // P @ V: P split hi/lo fp16 (exactness), V single fp16
#pragma unroll
        for (int ks2 = 0; ks2 < 8; ks2++) {
            float p00 = sc_[2*ks2][0],   p01 = sc_[2*ks2][1];
            float p02 = sc_[2*ks2][2],   p03 = sc_[2*ks2][3];
            float p10 = sc_[2*ks2+1][0], p11 = sc_[2*ks2+1][1];
            float p12 = sc_[2*ks2+1][2], p13 = sc_[2*ks2+1][3];
            u32 aPh[4], aPl[4];
            aPh[0] = pack_h2(p00, p01);
            aPh[1] = pack_h2(p02, p03);
            aPh[2] = pack_h2(p10, p11);
            aPh[3] = pack_h2(p12, p13);
            aPl[0] = pack_h2(h_lo(p00), h_lo(p01));
            aPl[1] = pack_h2(h_lo(p02), h_lo(p03));
            aPl[2] = pack_h2(h_lo(p10), h_lo(p11));
            aPl[3] = pack_h2(h_lo(p12), h_lo(p13));

            const u32 vr = (u32)(ks2 * 16) + frag_row;
#pragma unroll
            for (int nd = 0; nd < 4; nd++) {
                const u32 cByte = (u32)(nd * 32) + frag_col;
                u32 v0, v1, v2, v3;
                ldsm4t(sb + A_V + vr * 144 + cByte, v0, v1, v2, v3);
                int od0 = nd * 2, od1 = nd * 2 + 1;
                mma_f16(Oa[od0], aPh, v0, v1);
                mma_f16(Oa[od0], aPl, v0, v1);
                mma_f16(Oa[od1], aPh, v2, v3);
                mma_f16(Oa[od1], aPl, v2, v3);
            }
        }
    }

    float inv0 = 1.f / l0, inv1 = 1.f / l1;
    int qa = q0 + w * 16 + (lane >> 2);
    int qb = qa + 8;
    size_t baseA = (size_t)(b * T_ + qa) * D_ + h * DH_;
    size_t baseB = (size_t)(b * T_ + qb) * D_ + h * DH_;
#pragma unroll
    for (int od = 0; od < 8; od++) {
        int col = od * 8 + (lane & 3) * 2;
        float o0 = Oa[od][0] * inv0, o1 = Oa[od][1] * inv0;
        float o2 = Oa[od][2] * inv1, o3 = Oa[od][3] * inv1;
        *(u32*)(ctxH + baseA + col) = pack_h2(o0, o1);
        *(u32*)(ctxL + baseA + col) = pack_h2(h_lo(o0), h_lo(o1));
        *(u32*)(ctxH + baseB + col) = pack_h2(o2, o3);
        *(u32*)(ctxL + baseB + col) = pack_h2(h_lo(o2), h_lo(o3));
    }
}

// ---------------- residual + LayerNorm ---------------------------------------
__global__ __launch_bounds__(256)
void ln_kernel(const float* __restrict__ raw,
               const float* __restrict__ rw, const float* __restrict__ re,
               const float* __restrict__ rfull, int use_full,
               const float* __restrict__ gm, const float* __restrict__ bt,
               float* __restrict__ out, int final_mode,
               half* __restrict__ outH, half* __restrict__ outL)
{
    const int row = blockIdx.x;
    const int b = row / T_, t = row % T_;
    const float* rp = use_full
        ? rfull + (size_t)row * D_
        : (t < S_ ? rw + ((size_t)(b * S_ + t)) * D_
                  : re + ((size_t)(b * E_ + t - S_)) * D_);
    const float* x = raw + (size_t)row * D_;

    float vv[3];
    float s = 0.f, sq = 0.f;
#pragma unroll
    for (int i = 0; i < 3; i++) {
        int c = threadIdx.x + i * 256;
        float val = x[c] + rp[c];
        vv[i] = val;
        s += val;
        sq += val * val;
    }
    const int lane = threadIdx.x & 31, w = threadIdx.x >> 5;
#pragma unroll
    for (int o = 16; o; o >>= 1) {
        s  += __shfl_xor_sync(0xffffffffu, s,  o);
        sq += __shfl_xor_sync(0xffffffffu, sq, o);
    }
    __shared__ float ws[8], wq[8];
    __shared__ float sm, sv;
    if (lane == 0) { ws[w] = s; wq[w] = sq; }
    __syncthreads();
    if (threadIdx.x == 0) {
        float ts = 0.f, tq = 0.f;
#pragma unroll
        for (int i = 0; i < 8; i++) { ts += ws[i]; tq += wq[i]; }
        float mean = ts * (1.f / D_);
        sm = mean;
        sv = rsqrtf(tq * (1.f / D_) - mean * mean + 1e-12f);
    }
    __syncthreads();
    const float mean = sm, inv = sv;

    float* o = final_mode
        ? (t < S_ ? out + ((size_t)(b * S_ + t)) * D_
                  : out + (size_t)B_ * S_ * D_ + ((size_t)(b * E_ + t - S_)) * D_)
        : out + (size_t)row * D_;
#pragma unroll
    for (int i = 0; i < 3; i++) {
        int c = threadIdx.x + i * 256;
        float y = (vv[i] - mean) * inv * gm[c] + bt[c];
        o[c] = y;
        if (outH) {
            half h = __float2half_rn(y);
            outH[(size_t)row * D_ + c] = h;
            outL[(size_t)row * D_ + c] = __float2half_rn(y - __half2float(h));
        }
    }
}

// ---------------- host -------------------------------------------------------
extern "C" void kernel_launch(void* const* d_in, const int* in_sizes, int n_in,
                              void* d_out, int out_size)
{
    const float* word  = (const float*)d_in[0];
    const float* ent   = (const float*)d_in[1];
    const float* mask  = (const float*)d_in[2];
    const float* W_q   = (const float*)d_in[3],  *b_q    = (const float*)d_in[4];
    const float* W_k   = (const float*)d_in[5],  *b_k    = (const float*)d_in[6];
    const float* W_v   = (const float*)d_in[7],  *b_v    = (const float*)d_in[8];
    const float* W_w2e = (const float*)d_in[9],  *b_w2e  = (const float*)d_in[10];
    const float* W_e2w = (const float*)d_in[11], *b_e2w  = (const float*)d_in[12];
    const float* W_e2e = (const float*)d_in[13], *b_e2e  = (const float*)d_in[14];
    const float* W_ao  = (const float*)d_in[15], *b_ao   = (const float*)d_in[16];
    const float* gm_ao = (const float*)d_in[17], *bt_ao  = (const float*)d_in[18];
    const float* W_i   = (const float*)d_in[19], *b_i    = (const float*)d_in[20];
    const float* W_o   = (const float*)d_in[21], *b_o    = (const float*)d_in[22];
    const float* gm_o  = (const float*)d_in[23], *bt_o   = (const float*)d_in[24];

    void* p;
    cudaGetSymbolAddress(&p, g_ao);    float* d_ao  = (float*)p;
    cudaGetSymbolAddress(&p, g_tmp);   float* d_tmp = (float*)p;

    half *wordH,*wordL,*entH,*entL,*q1H,*q1L,*q2H,*q2L,*kH,*vH,*ctxH,*ctxL,*aoH,*aoL,*intH,*intL;
    cudaGetSymbolAddress(&p, g_word_h); wordH = (half*)p;
    cudaGetSymbolAddress(&p, g_word_l); wordL = (half*)p;
    cudaGetSymbolAddress(&p, g_ent_h);  entH  = (half*)p;
    cudaGetSymbolAddress(&p, g_ent_l);  entL  = (half*)p;
    cudaGetSymbolAddress(&p, g_q1h);    q1H   = (half*)p;
    cudaGetSymbolAddress(&p, g_q1l);    q1L   = (half*)p;
    cudaGetSymbolAddress(&p, g_q2h);    q2H   = (half*)p;
    cudaGetSymbolAddress(&p, g_q2l);    q2L   = (half*)p;
    cudaGetSymbolAddress(&p, g_kh);     kH    = (half*)p;
    cudaGetSymbolAddress(&p, g_vh);     vH    = (half*)p;
    cudaGetSymbolAddress(&p, g_ctx_h);  ctxH  = (half*)p;
    cudaGetSymbolAddress(&p, g_ctx_l);  ctxL  = (half*)p;
    cudaGetSymbolAddress(&p, g_ao_h);   aoH   = (half*)p;
    cudaGetSymbolAddress(&p, g_ao_l);   aoL   = (half*)p;
    cudaGetSymbolAddress(&p, g_int_h);  intH  = (half*)p;
    cudaGetSymbolAddress(&p, g_int_l);  intL  = (half*)p;

    half *wpw,*wpe,*wao,*wi,*wo;
    cudaGetSymbolAddress(&p, g_wpw); wpw = (half*)p;
    cudaGetSymbolAddress(&p, g_wpe); wpe = (half*)p;
    cudaGetSymbolAddress(&p, g_wao); wao = (half*)p;
    cudaGetSymbolAddress(&p, g_wi);  wi  = (half*)p;
    cudaGetSymbolAddress(&p, g_wo);  wo  = (half*)p;

    cudaFuncSetAttribute(gemm_tc, cudaFuncAttributeMaxDynamicSharedMemorySize, SMEM_DYN);
    cudaFuncSetAttribute(attn_tc, cudaFuncAttributeMaxDynamicSharedMemorySize, ATT_SMEM);

    const dim3 thr(256);
    const int MW = B_ * S_;
    const int ME = B_ * E_;
    const size_t WSLICE = (size_t)D_ * D_;

    // weight transpose -> packed fp16
    wconv<<<dim3(D_/32,  D_/32),  thr>>>(W_q,   wpw + 0*WSLICE, D_, D_);
    wconv<<<dim3(D_/32,  D_/32),  thr>>>(W_w2e, wpw + 1*WSLICE, D_, D_);
    wconv<<<dim3(D_/32,  D_/32),  thr>>>(W_k,   wpw + 2*WSLICE, D_, D_);
    wconv<<<dim3(D_/32,  D_/32),  thr>>>(W_v,   wpw + 3*WSLICE, D_, D_);
    wconv<<<dim3(D_/32,  D_/32),  thr>>>(W_e2w, wpe + 0*WSLICE, D_, D_);
    wconv<<<dim3(D_/32,  D_/32),  thr>>>(W_e2e, wpe + 1*WSLICE, D_, D_);
    wconv<<<dim3(D_/32,  D_/32),  thr>>>(W_k,   wpe + 2*WSLICE, D_, D_);
    wconv<<<dim3(D_/32,  D_/32),  thr>>>(W_v,   wpe + 3*WSLICE, D_, D_);
    wconv<<<dim3(D_/32,  D_/32),  thr>>>(W_ao,  wao, D_,  D_);
    wconv<<<dim3(FF_/32, D_/32),  thr>>>(W_i,   wi,  D_,  FF_);
    wconv<<<dim3(D_/32,  FF_/32), thr>>>(W_o,   wo,  FF_, D_);

    aconv<<<(unsigned)((size_t)MW * D_ / 256), thr>>>(word, wordH, wordL);
    aconv<<<(unsigned)((size_t)ME * D_ / 256), thr>>>(ent,  entH,  entL);

    // packed projections (word + entity), interleaved into [B,T,D]
    // q1/q2 need hi+lo (A-side downstream); k/v single (B-side downstream)
    Dest4 dpW;
    dpW.d[0] = { nullptr, q1H, q1L,     b_q   };
    dpW.d[1] = { nullptr, q2H, q2L,     b_w2e };
    dpW.d[2] = { nullptr, kH,  nullptr, b_k   };
    dpW.d[3] = { nullptr, vH,  nullptr, b_v   };
    gemm_tc<<<dim3(4*D_/128, MW/128), thr, SMEM_DYN>>>(wordH, wordL, wpw,
        dpW, MW, 4*D_, D_, D_, S_, 0, 2);

    Dest4 dpE;
    dpE.d[0] = { nullptr, q1H, q1L,     b_e2w };
    dpE.d[1] = { nullptr, q2H, q2L,     b_e2e };
    dpE.d[2] = { nullptr, kH,  nullptr, b_k   };
    dpE.d[3] = { nullptr, vH,  nullptr, b_v   };
    gemm_tc<<<dim3(4*D_/128, ME/128), thr, SMEM_DYN>>>(entH, entL, wpe,
        dpE, ME, 4*D_, D_, D_, E_, S_, 2);

    // attention -> split ctx
    attn_tc<<<dim3(T_/128, H_, B_), thr, ATT_SMEM>>>(q1H, q1L, q2H, q2L, kH, vH,
                                                     mask, ctxH, ctxL);

    // AO projection + LN
    Dest4 dpA;
    dpA.d[0] = { d_tmp, nullptr, nullptr, b_ao };
    dpA.d[1] = dpA.d[0]; dpA.d[2] = dpA.d[0]; dpA.d[3] = dpA.d[0];
    gemm_tc<<<dim3(D_/128, NT_/128), thr, SMEM_DYN>>>(ctxH, ctxL, wao,
        dpA, NT_, D_, D_, D_, NT_, 0, 0);
    ln_kernel<<<NT_, thr>>>(d_tmp, word, ent, d_ao, 0, gm_ao, bt_ao, d_ao, 0, aoH, aoL);

    // FFN1 (+GELU, h/l out)
    Dest4 dpI;
    dpI.d[0] = { nullptr, intH, intL, b_i };
    dpI.d[1] = dpI.d[0]; dpI.d[2] = dpI.d[0]; dpI.d[3] = dpI.d[0];
    gemm_tc<<<dim3(FF_/128, NT_/128), thr, SMEM_DYN>>>(aoH, aoL, wi,
        dpI, NT_, FF_, D_, FF_, NT_, 0, 1);

    // FFN2
    Dest4 dpO;
    dpO.d[0] = { d_tmp, nullptr, nullptr, b_o };
    dpO.d[1] = dpO.d[0]; dpO.d[2] = dpO.d[0]; dpO.d[3] = dpO.d[0];
    gemm_tc<<<dim3(D_/128, NT_/128), thr, SMEM_DYN>>>(intH, intL, wo,
        dpO, NT_, D_, FF_, D_, NT_, 0, 0);

    // final LN -> split (word, entity) output
    ln_kernel<<<NT_, thr>>>(d_tmp, nullptr, nullptr, d_ao, 1, gm_o, bt_o,
                            (float*)d_out, 1, nullptr, nullptr);
}

// round 10
// speedup vs baseline: 2.5713x; 1.5018x over previous
#include <cuda_runtime.h>
#include <cuda_fp16.h>
#include <stdint.h>
#include <math.h>

// Shapes (fixed for this problem)
#define B_  16
#define S_  512
#define E_  128
#define T_  640      // S_ + E_
#define D_  768
#define H_  12
#define DH_ 64
#define FF_ 3072
#define NT_ (B_*T_) // 10240

typedef unsigned int       u32;
typedef unsigned long long u64;

// ---------------- scratch (__device__ globals) ------------------------------
__device__ float g_ao [(size_t)NT_*D_];
__device__ float g_tmp[(size_t)NT_*D_];

// fp16 activations (single precision except Q which keeps hi/lo for attention)
__device__ half g_word[(size_t)B_*S_*D_];
__device__ half g_ent [(size_t)B_*E_*D_];
__device__ half g_q1h[(size_t)NT_*D_], g_q1l[(size_t)NT_*D_];
__device__ half g_q2h[(size_t)NT_*D_], g_q2l[(size_t)NT_*D_];
__device__ half g_kh [(size_t)NT_*D_];
__device__ half g_vh [(size_t)NT_*D_];
__device__ half g_ctx[(size_t)NT_*D_];
__device__ half g_aoh[(size_t)NT_*D_];
__device__ half g_int[(size_t)NT_*FF_];

// packed fp16 weights ([N,K] row-major)
__device__ half g_wpw[4*D_*D_];   // word: q | w2e | k | v
__device__ half g_wpe[4*D_*D_];   // ent:  e2w | e2e | k | v
__device__ half g_wao[D_*D_];
__device__ half g_wi [FF_*D_];
__device__ half g_wo [D_*FF_];

struct DestPack { float* y; half* yh; half* yl; const float* bias; };
struct Dest4 { DestPack d[4]; };

// ---------------- PTX helpers ----------------------------------------------
__device__ __forceinline__ u32 smem_u32(const void* p) {
    u32 a;
    asm("{ .reg .u64 t; cvta.to.shared.u64 t, %1; cvt.u32.u64 %0, t; }" : "=r"(a) : "l"(p));
    return a;
}
__device__ __forceinline__ void cpa16(u32 s, const void* g) {
    asm volatile("cp.async.cg.shared.global [%0], [%1], 16;" :: "r"(s), "l"(g));
}
__device__ __forceinline__ void ldsm4(u32 addr, u32& r0, u32& r1, u32& r2, u32& r3) {
    asm volatile("ldmatrix.sync.aligned.m8n8.x4.shared.b16 {%0,%1,%2,%3}, [%4];"
                 : "=r"(r0), "=r"(r1), "=r"(r2), "=r"(r3) : "r"(addr));
}
__device__ __forceinline__ void ldsm4t(u32 addr, u32& r0, u32& r1, u32& r2, u32& r3) {
    asm volatile("ldmatrix.sync.aligned.m8n8.x4.trans.shared.b16 {%0,%1,%2,%3}, [%4];"
                 : "=r"(r0), "=r"(r1), "=r"(r2), "=r"(r3) : "r"(addr));
}
__device__ __forceinline__ void mma_f16(float* c, const u32* a, u32 b0, u32 b1) {
    asm volatile(
        "mma.sync.aligned.m16n8k16.row.col.f32.f16.f16.f32 "
        "{%0,%1,%2,%3}, {%4,%5,%6,%7}, {%8,%9}, {%0,%1,%2,%3};"
        : "+f"(c[0]), "+f"(c[1]), "+f"(c[2]), "+f"(c[3])
        : "r"(a[0]), "r"(a[1]), "r"(a[2]), "r"(a[3]), "r"(b0), "r"(b1));
}
__device__ __forceinline__ float fexp(float x) {
    x = fmaxf(x, -80.f);
    float y = x * 1.4426950408889634f;
    int n = __float2int_rn(y);
    float f = y - (float)n;
    float p = 1.33336e-3f;
    p = fmaf(p, f, 9.61813e-3f);
    p = fmaf(p, f, 5.5504109e-2f);
    p = fmaf(p, f, 2.4022651e-1f);
    p = fmaf(p, f, 6.9314718e-1f);
    p = fmaf(p, f, 1.0f);
    return p * __int_as_float((n + 127) << 23);
}
__device__ __forceinline__ u32 pack_h2(float a, float b) {
    __half2 t = __floats2half2_rn(a, b);
    return *(u32*)&t;
}
__device__ __forceinline__ float h_lo(float v) {
    return v - __half2float(__float2half_rn(v));
}

// ---------------- weight transpose -> fp16 -----------------------------------
__global__ __launch_bounds__(256)
void wconv(const float* __restrict__ W, half* __restrict__ Wt, int K, int N)
{
    __shared__ float t[32][33];
    const int n0 = blockIdx.x * 32, k0 = blockIdx.y * 32;
    const int tx = threadIdx.x & 31, ty = threadIdx.x >> 5;
#pragma unroll
    for (int i = 0; i < 4; i++)
        t[ty + i*8][tx] = W[(size_t)(k0 + ty + i*8) * N + n0 + tx];
    __syncthreads();
#pragma unroll
    for (int i = 0; i < 4; i++)
        Wt[(size_t)(n0 + ty + i*8) * K + k0 + tx] = __float2half_rn(t[tx][ty + i*8]);
}

// ---------------- activation convert (fp16 single) ---------------------------
__global__ __launch_bounds__(256)
void aconv(const float* __restrict__ x, half* __restrict__ h)
{
    size_t i = (size_t)blockIdx.x * 256 + threadIdx.x;
    h[i] = __float2half_rn(x[i]);
}

// ---------------- fp16 GEMM (128x128 CTA, 32x64 warp, 1 MMA per k16) ---------
// Y = A[m,:] @ Bt[n,:] + bias ; dest by n0/nsplit; row remap seg/rowoff.
// act==0: fp32 out. act==1: GELU + fp16 out (hi, + lo if yl). act==2: bias + fp16 out.
#define BK_     32
#define TILE_BY (128*80)              // 10240 B per tile (80B padded rows)
#define STG_BY  (2*TILE_BY)           // 20480 (A, B)
#define SMEM_DYN (3*STG_BY)           // 61440

__global__ __launch_bounds__(256, 1)
void gemm_tc(const half* __restrict__ A, const half* __restrict__ Bt,
             Dest4 dp, int M, int N, int K, int nsplit, int seg, int rowoff, int act)
{
    extern __shared__ char smem[];
    const u32 sb = smem_u32(smem);
    const int tid  = threadIdx.x;
    const int lane = tid & 31;
    const int wid  = tid >> 5;
    const int wm   = wid >> 1;
    const int wn   = wid & 1;
    const int n0 = blockIdx.x * 128;
    const int m0 = blockIdx.y * 128;
    const int nk = K / BK_;

    const half* srcs[2] = { A + (size_t)m0 * K, Bt + (size_t)n0 * K };

    auto load_chunk = [&](int s, int kc) {
        const int k0c = kc * BK_;
#pragma unroll
        for (int i = 0; i < 4; i++) {
            int c   = tid + i * 256;      // 0..1023
            int t   = c >> 9;             // 0..1
            int cc  = c & 511;
            int r   = cc >> 2;
            int c16 = cc & 3;
            cpa16(sb + (u32)s * STG_BY + (u32)t * TILE_BY + (u32)(r * 80 + c16 * 16),
                  srcs[t] + k0c + (size_t)r * K + c16 * 8);
        }
        asm volatile("cp.async.commit_group;" ::: "memory");
    };

    float acc[2][8][4];
#pragma unroll
    for (int mt = 0; mt < 2; mt++)
#pragma unroll
        for (int nt = 0; nt < 8; nt++)
#pragma unroll
            for (int j = 0; j < 4; j++) acc[mt][nt][j] = 0.f;

    const u32 frag_row = (u32)(lane & 15);
    const u32 frag_col = (u32)((lane >> 4) << 4);

    load_chunk(0, 0);
    load_chunk(1, 1);

    for (int kc = 0; kc < nk; kc++) {
        const int s = kc % 3;
        if (kc + 2 < nk) {
            load_chunk((kc + 2) % 3, kc + 2);
            asm volatile("cp.async.wait_group 2;" ::: "memory");
        } else if (kc + 1 < nk) {
            asm volatile("cp.async.wait_group 1;" ::: "memory");
        } else {
            asm volatile("cp.async.wait_group 0;" ::: "memory");
        }
        __syncthreads();

        const u32 stg = sb + (u32)s * STG_BY;
        const u32 aBase = stg;
        const u32 bBase = stg + TILE_BY;

#pragma unroll
        for (int ks = 0; ks < 2; ks++) {
            const u32 kByte = (u32)(ks * 32) + frag_col;
            u32 a[2][4], bb[4][4];
#pragma unroll
            for (int mt = 0; mt < 2; mt++) {
                u32 ro = (u32)(wm * 32 + mt * 16) + frag_row;
                ldsm4(aBase + ro * 80 + kByte, a[mt][0], a[mt][1], a[mt][2], a[mt][3]);
            }
#pragma unroll
            for (int np = 0; np < 4; np++) {
                u32 ro = (u32)(wn * 64 + np * 16) + frag_row;
                ldsm4(bBase + ro * 80 + kByte, bb[np][0], bb[np][1], bb[np][2], bb[np][3]);
            }
#pragma unroll
            for (int mt = 0; mt < 2; mt++)
#pragma unroll
                for (int nt = 0; nt < 8; nt++) {
                    int np = nt >> 1, sel = nt & 1;
                    mma_f16(acc[mt][nt], a[mt], bb[np][sel], bb[np][sel + 2]);
                }
        }
        __syncthreads();
    }

    // epilogue: dest by n-block
    const int di = n0 / nsplit;
    float* Y  = dp.d[di].y;
    half* Yh  = dp.d[di].yh;
    half* Yl  = dp.d[di].yl;
    const float* bias = dp.d[di].bias;
    const int ncol_off = di * nsplit;

#pragma unroll
    for (int mt = 0; mt < 2; mt++) {
#pragma unroll
        for (int half_ = 0; half_ < 2; half_++) {
            int mlog = m0 + wm * 32 + mt * 16 + (lane >> 2) + half_ * 8;
            size_t phys = (size_t)(mlog / seg) * T_ + (mlog % seg) + rowoff;
#pragma unroll
            for (int nt = 0; nt < 8; nt++) {
                int col = n0 + wn * 64 + nt * 8 + (lane & 3) * 2 - ncol_off;
                float v0 = acc[mt][nt][half_ * 2 + 0] + bias[col + 0];
                float v1 = acc[mt][nt][half_ * 2 + 1] + bias[col + 1];
                if (act == 0) {
                    *(float2*)(Y + phys * (size_t)nsplit + col) = make_float2(v0, v1);
                } else {
                    if (act == 1) {
                        v0 = 0.5f * v0 * (1.0f + erff(v0 * 0.70710678f));
                        v1 = 0.5f * v1 * (1.0f + erff(v1 * 0.70710678f));
                    }
                    *(u32*)(Yh + phys * (size_t)nsplit + col) = pack_h2(v0, v1);
                    if (Yl)
                        *(u32*)(Yl + phys * (size_t)nsplit + col) = pack_h2(h_lo(v0), h_lo(v1));
                }
            }
        }
    }
}

// ---------------- fp16 flash attention (R9, unchanged) -----------------------
// Q split hi/lo (A side); K, V single fp16 (B side). 6 tiles of 128x144B.
#define QT_BY   (128*144)
#define A_Q1H   0
#define A_Q1L   (1*QT_BY)
#define A_Q2H   (2*QT_BY)
#define A_Q2L   (3*QT_BY)
#define A_K     (4*QT_BY)
#define A_V     (5*QT_BY)
#define A_MS    (6*QT_BY)
#define ATT_SMEM (6*QT_BY + 512)     // 111104

__global__ __launch_bounds__(256, 1)
void attn_tc(const half* __restrict__ q1h, const half* __restrict__ q1l,
             const half* __restrict__ q2h, const half* __restrict__ q2l,
             const half* __restrict__ kh,  const half* __restrict__ vh,
             const float* __restrict__ mask,
             half* __restrict__ ctxH)
{
    extern __shared__ char smem[];
    const u32 sb = smem_u32(smem);
    float* maskS = (float*)(smem + A_MS);

    const int b  = blockIdx.z;
    const int h  = blockIdx.y;
    const int q0 = blockIdx.x * 128;
    const int tid  = threadIdx.x;
    const int lane = tid & 31;
    const int w    = tid >> 5;

    const u32 frag_row = (u32)(lane & 15);
    const u32 frag_col = (u32)((lane >> 4) << 4);

    {
        const half* srcQ[4] = { q1h, q1l, q2h, q2l };
#pragma unroll
        for (int i = 0; i < 16; i++) {
            int idx = tid + i * 256;
            int arr = idx >> 10;
            int rr  = (idx >> 3) & 127;
            int ch  = idx & 7;
            cpa16(sb + (u32)(arr * QT_BY + rr * 144 + ch * 16),
                  srcQ[arr] + (size_t)(b * T_ + q0 + rr) * D_ + h * DH_ + ch * 8);
        }
        asm volatile("cp.async.commit_group;" ::: "memory");
    }

    float Oa[8][4];
#pragma unroll
    for (int od = 0; od < 8; od++)
#pragma unroll
        for (int j = 0; j < 4; j++) Oa[od][j] = 0.f;
    float m0 = -1e30f, m1 = -1e30f, l0 = 0.f, l1 = 0.f;

    for (int kt = 0; kt < 5; kt++) {
        __syncthreads();
        {
            const half* srcT[2] = { kh, vh };
#pragma unroll
            for (int i = 0; i < 8; i++) {
                int idx = tid + i * 256;
                int arr = idx >> 10;
                int rr  = (idx >> 3) & 127;
                int ch  = idx & 7;
                cpa16(sb + (u32)(A_K + arr * QT_BY + rr * 144 + ch * 16),
                      srcT[arr] + (size_t)(b * T_ + kt * 128 + rr) * D_ + h * DH_ + ch * 8);
            }
            if (tid < 128) maskS[tid] = mask[b * T_ + kt * 128 + tid];
            asm volatile("cp.async.commit_group;" ::: "memory");
            asm volatile("cp.async.wait_group 0;" ::: "memory");
        }
        __syncthreads();

        const u32 qbh = sb + (u32)((kt < 4) ? A_Q1H : A_Q2H);
        const u32 qbl = qbh + QT_BY;

        float sc_[16][4];
#pragma unroll
        for (int nt = 0; nt < 16; nt++)
#pragma unroll
            for (int j = 0; j < 4; j++) sc_[nt][j] = 0.f;

#pragma unroll
        for (int ks = 0; ks < 4; ks++) {
            const u32 kByte = (u32)(ks * 32) + frag_col;
            u32 ah[4], al[4], bh[8][4];
            u32 ro = (u32)(w * 16) + frag_row;
            ldsm4(qbh + ro * 144 + kByte, ah[0], ah[1], ah[2], ah[3]);
            ldsm4(qbl + ro * 144 + kByte, al[0], al[1], al[2], al[3]);
#pragma unroll
            for (int np = 0; np < 8; np++) {
                u32 kr = (u32)(np * 16) + frag_row;
                ldsm4(sb + A_K + kr * 144 + kByte, bh[np][0], bh[np][1], bh[np][2], bh[np][3]);
            }
#pragma unroll
            for (int nt = 0; nt < 16; nt++) {
                int np = nt >> 1, sel = nt & 1;
                u32 b0 = bh[np][sel], b1 = bh[np][sel + 2];
                mma_f16(sc_[nt], ah, b0, b1);
                mma_f16(sc_[nt], al, b0, b1);
            }
        }

        float rmax0 = -1e30f, rmax1 = -1e30f;
#pragma unroll
        for (int nt = 0; nt < 16; nt++) {
            int cbase = nt * 8 + (lane & 3) * 2;
            float mk0 = maskS[cbase], mk1 = maskS[cbase + 1];
            sc_[nt][0] = fmaf(sc_[nt][0], 0.125f, mk0);
            sc_[nt][1] = fmaf(sc_[nt][1], 0.125f, mk1);
            sc_[nt][2] = fmaf(sc_[nt][2], 0.125f, mk0);
            sc_[nt][3] = fmaf(sc_[nt][3], 0.125f, mk1);
            rmax0 = fmaxf(rmax0, fmaxf(sc_[nt][0], sc_[nt][1]));
            rmax1 = fmaxf(rmax1, fmaxf(sc_[nt][2], sc_[nt][3]));
        }
        rmax0 = fmaxf(rmax0, __shfl_xor_sync(0xffffffffu, rmax0, 1));
        rmax0 = fmaxf(rmax0, __shfl_xor_sync(0xffffffffu, rmax0, 2));
        rmax1 = fmaxf(rmax1, __shfl_xor_sync(0xffffffffu, rmax1, 1));
        rmax1 = fmaxf(rmax1, __shfl_xor_sync(0xffffffffu, rmax1, 2));

        float mn0 = fmaxf(m0, rmax0), mn1 = fmaxf(m1, rmax1);
        float f0 = fexp(m0 - mn0), f1 = fexp(m1 - mn1);
        float rs0 = 0.f, rs1 = 0.f;
#pragma unroll
        for (int nt = 0; nt < 16; nt++) {
            sc_[nt][0] = fexp(sc_[nt][0] - mn0);
            sc_[nt][1] = fexp(sc_[nt][1] - mn0);
            sc_[nt][2] = fexp(sc_[nt][2] - mn1);
            sc_[nt][3] = fexp(sc_[nt][3] - mn1);
            rs0 += sc_[nt][0] + sc_[nt][1];
            rs1 += sc_[nt][2] + sc_[nt][3];
        }
        rs0 += __shfl_xor_sync(0xffffffffu, rs0, 1);
        rs0 += __shfl_xor_sync(0xffffffffu, rs0, 2);
        rs1 += __shfl_xor_sync(0xffffffffu, rs1, 1);
        rs1 += __shfl_xor_sync(0xffffffffu, rs1, 2);
        l0 = l0 * f0 + rs0;
        l1 = l1 * f1 + rs1;
        m0 = mn0; m1 = mn1;
#pragma unroll
        for (int od = 0; od < 8; od++) {
            Oa[od][0] *= f0; Oa[od][1] *= f0;
            Oa[od][2] *= f1; Oa[od][3] *= f1;
        }

        // P @ V: P split hi/lo fp16, V single fp16
#pragma unroll
        for (int ks2 = 0; ks2 < 8; ks2++) {
            float p00 = sc_[2*ks2][0],   p01 = sc_[2*ks2][1];
            float p02 = sc_[2*ks2][2],   p03 = sc_[2*ks2][3];
            float p10 = sc_[2*ks2+1][0], p11 = sc_[2*ks2+1][1];
            float p12 = sc_[2*ks2+1][2], p13 = sc_[2*ks2+1][3];
            u32 aPh[4], aPl[4];
            aPh[0] = pack_h2(p00, p01);
            aPh[1] = pack_h2(p02, p03);
            aPh[2] = pack_h2(p10, p11);
            aPh[3] = pack_h2(p12, p13);
            aPl[0] = pack_h2(h_lo(p00), h_lo(p01));
            aPl[1] = pack_h2(h_lo(p02), h_lo(p03));
            aPl[2] = pack_h2(h_lo(p10), h_lo(p11));
            aPl[3] = pack_h2(h_lo(p12), h_lo(p13));

            const u32 vr = (u32)(ks2 * 16) + frag_row;
#pragma unroll
            for (int nd = 0; nd < 4; nd++) {
                const u32 cByte = (u32)(nd * 32) + frag_col;
                u32 v0, v1, v2, v3;
                ldsm4t(sb + A_V + vr * 144 + cByte, v0, v1, v2, v3);
                int od0 = nd * 2, od1 = nd * 2 + 1;
                mma_f16(Oa[od0], aPh, v0, v1);
                mma_f16(Oa[od0], aPl, v0, v1);
                mma_f16(Oa[od1], aPh, v2, v3);
                mma_f16(Oa[od1], aPl, v2, v3);
            }
        }
    }

    float inv0 = 1.f / l0, inv1 = 1.f / l1;
    int qa = q0 + w * 16 + (lane >> 2);
    int qb = qa + 8;
    size_t baseA = (size_t)(b * T_ + qa) * D_ + h * DH_;
    size_t baseB = (size_t)(b * T_ + qb) * D_ + h * DH_;
#pragma unroll
    for (int od = 0; od < 8; od++) {
        int col = od * 8 + (lane & 3) * 2;
        *(u32*)(ctxH + baseA + col) = pack_h2(Oa[od][0] * inv0, Oa[od][1] * inv0);
        *(u32*)(ctxH + baseB + col) = pack_h2(Oa[od][2] * inv1, Oa[od][3] * inv1);
    }
}

// ---------------- residual + LayerNorm ---------------------------------------
__global__ __launch_bounds__(256)
void ln_kernel(const float* __restrict__ raw,
               const float* __restrict__ rw, const float* __restrict__ re,
               const float* __restrict__ rfull, int use_full,
               const float* __restrict__ gm, const float* __restrict__ bt,
               float* __restrict__ out, int final_mode,
               half* __restrict__ outH)
{
    const int row = blockIdx.x;
    const int b = row / T_, t = row % T_;
    const float* rp = use_full
        ? rfull + (size_t)row * D_
        : (t < S_ ? rw + ((size_t)(b * S_ + t)) * D_
                  : re + ((size_t)(b * E_ + t - S_)) * D_);
    const float* x = raw + (size_t)row * D_;

    float vv[3];
    float s = 0.f, sq = 0.f;
#pragma unroll
    for (int i = 0; i < 3; i++) {
        int c = threadIdx.x + i * 256;
        float val = x[c] + rp[c];
        vv[i] = val;
        s += val;
        sq += val * val;
    }
    const int lane = threadIdx.x & 31, w = threadIdx.x >> 5;
#pragma unroll
    for (int o = 16; o; o >>= 1) {
        s  += __shfl_xor_sync(0xffffffffu, s,  o);
        sq += __shfl_xor_sync(0xffffffffu, sq, o);
    }
    __shared__ float ws[8], wq[8];
    __shared__ float sm, sv;
    if (lane == 0) { ws[w] = s; wq[w] = sq; }
    __syncthreads();
    if (threadIdx.x == 0) {
        float ts = 0.f, tq = 0.f;
#pragma unroll
        for (int i = 0; i < 8; i++) { ts += ws[i]; tq += wq[i]; }
        float mean = ts * (1.f / D_);
        sm = mean;
        sv = rsqrtf(tq * (1.f / D_) - mean * mean + 1e-12f);
    }
    __syncthreads();
    const float mean = sm, inv = sv;

    float* o = final_mode
        ? (t < S_ ? out + ((size_t)(b * S_ + t)) * D_
                  : out + (size_t)B_ * S_ * D_ + ((size_t)(b * E_ + t - S_)) * D_)
        : out + (size_t)row * D_;
#pragma unroll
    for (int i = 0; i < 3; i++) {
        int c = threadIdx.x + i * 256;
        float y = (vv[i] - mean) * inv * gm[c] + bt[c];
        o[c] = y;
        if (outH)
            outH[(size_t)row * D_ + c] = __float2half_rn(y);
    }
}

// ---------------- host -------------------------------------------------------
extern "C" void kernel_launch(void* const* d_in, const int* in_sizes, int n_in,
                              void* d_out, int out_size)
{
    const float* word  = (const float*)d_in[0];
    const float* ent   = (const float*)d_in[1];
    const float* mask  = (const float*)d_in[2];
    const float* W_q   = (const float*)d_in[3],  *b_q    = (const float*)d_in[4];
    const float* W_k   = (const float*)d_in[5],  *b_k    = (const float*)d_in[6];
    const float* W_v   = (const float*)d_in[7],  *b_v    = (const float*)d_in[8];
    const float* W_w2e = (const float*)d_in[9],  *b_w2e  = (const float*)d_in[10];
    const float* W_e2w = (const float*)d_in[11], *b_e2w  = (const float*)d_in[12];
    const float* W_e2e = (const float*)d_in[13], *b_e2e  = (const float*)d_in[14];
    const float* W_ao  = (const float*)d_in[15], *b_ao   = (const float*)d_in[16];
    const float* gm_ao = (const float*)d_in[17], *bt_ao  = (const float*)d_in[18];
    const float* W_i   = (const float*)d_in[19], *b_i    = (const float*)d_in[20];
    const float* W_o   = (const float*)d_in[21], *b_o    = (const float*)d_in[22];
    const float* gm_o  = (const float*)d_in[23], *bt_o   = (const float*)d_in[24];

    void* p;
    cudaGetSymbolAddress(&p, g_ao);    float* d_ao  = (float*)p;
    cudaGetSymbolAddress(&p, g_tmp);   float* d_tmp = (float*)p;

    half *wordF,*entF,*q1H,*q1L,*q2H,*q2L,*kH,*vH,*ctxF,*aoF,*intF;
    cudaGetSymbolAddress(&p, g_word); wordF = (half*)p;
    cudaGetSymbolAddress(&p, g_ent);  entF  = (half*)p;
    cudaGetSymbolAddress(&p, g_q1h);  q1H   = (half*)p;
    cudaGetSymbolAddress(&p, g_q1l);  q1L   = (half*)p;
    cudaGetSymbolAddress(&p, g_q2h);  q2H   = (half*)p;
    cudaGetSymbolAddress(&p, g_q2l);  q2L   = (half*)p;
    cudaGetSymbolAddress(&p, g_kh);   kH    = (half*)p;
    cudaGetSymbolAddress(&p, g_vh);   vH    = (half*)p;
    cudaGetSymbolAddress(&p, g_ctx);  ctxF  = (half*)p;
    cudaGetSymbolAddress(&p, g_aoh);  aoF   = (half*)p;
    cudaGetSymbolAddress(&p, g_int);  intF  = (half*)p;

    half *wpw,*wpe,*wao,*wi,*wo;
    cudaGetSymbolAddress(&p, g_wpw); wpw = (half*)p;
    cudaGetSymbolAddress(&p, g_wpe); wpe = (half*)p;
    cudaGetSymbolAddress(&p, g_wao); wao = (half*)p;
    cudaGetSymbolAddress(&p, g_wi);  wi  = (half*)p;
    cudaGetSymbolAddress(&p, g_wo);  wo  = (half*)p;

    cudaFuncSetAttribute(gemm_tc, cudaFuncAttributeMaxDynamicSharedMemorySize, SMEM_DYN);
    cudaFuncSetAttribute(attn_tc, cudaFuncAttributeMaxDynamicSharedMemorySize, ATT_SMEM);

    const dim3 thr(256);
    const int MW = B_ * S_;
    const int ME = B_ * E_;
    const size_t WSLICE = (size_t)D_ * D_;

    // weight transpose -> packed fp16
    wconv<<<dim3(D_/32,  D_/32),  thr>>>(W_q,   wpw + 0*WSLICE, D_, D_);
    wconv<<<dim3(D_/32,  D_/32),  thr>>>(W_w2e, wpw + 1*WSLICE, D_, D_);
    wconv<<<dim3(D_/32,  D_/32),  thr>>>(W_k,   wpw + 2*WSLICE, D_, D_);
    wconv<<<dim3(D_/32,  D_/32),  thr>>>(W_v,   wpw + 3*WSLICE, D_, D_);
    wconv<<<dim3(D_/32,  D_/32),  thr>>>(W_e2w, wpe + 0*WSLICE, D_, D_);
    wconv<<<dim3(D_/32,  D_/32),  thr>>>(W_e2e, wpe + 1*WSLICE, D_, D_);
    wconv<<<dim3(D_/32,  D_/32),  thr>>>(W_k,   wpe + 2*WSLICE, D_, D_);
    wconv<<<dim3(D_/32,  D_/32),  thr>>>(W_v,   wpe + 3*WSLICE, D_, D_);
    wconv<<<dim3(D_/32,  D_/32),  thr>>>(W_ao,  wao, D_,  D_);
    wconv<<<dim3(FF_/32, D_/32),  thr>>>(W_i,   wi,  D_,  FF_);
    wconv<<<dim3(D_/32,  FF_/32), thr>>>(W_o,   wo,  FF_, D_);

    aconv<<<(unsigned)((size_t)MW * D_ / 256), thr>>>(word, wordF);
    aconv<<<(unsigned)((size_t)ME * D_ / 256), thr>>>(ent,  entF);

    // packed projections (word + entity), interleaved into [B,T,D]
    // q1/q2 need hi+lo (attention A-side); k/v single
    Dest4 dpW;
    dpW.d[0] = { nullptr, q1H, q1L,     b_q   };
    dpW.d[1] = { nullptr, q2H, q2L,     b_w2e };
    dpW.d[2] = { nullptr, kH,  nullptr, b_k   };
    dpW.d[3] = { nullptr, vH,  nullptr, b_v   };
    gemm_tc<<<dim3(4*D_/128, MW/128), thr, SMEM_DYN>>>(wordF, wpw,
        dpW, MW, 4*D_, D_, D_, S_, 0, 2);

    Dest4 dpE;
    dpE.d[0] = { nullptr, q1H, q1L,     b_e2w };
    dpE.d[1] = { nullptr, q2H, q2L,     b_e2e };
    dpE.d[2] = { nullptr, kH,  nullptr, b_k   };
    dpE.d[3] = { nullptr, vH,  nullptr, b_v   };
    gemm_tc<<<dim3(4*D_/128, ME/128), thr, SMEM_DYN>>>(entF, wpe,
        dpE, ME, 4*D_, D_, D_, E_, S_, 2);

    // attention -> fp16 ctx
    attn_tc<<<dim3(T_/128, H_, B_), thr, ATT_SMEM>>>(q1H, q1L, q2H, q2L, kH, vH,
                                                     mask, ctxF);

    // AO projection + LN (LN emits fp16 ao for FFN1)
    Dest4 dpA;
    dpA.d[0] = { d_tmp, nullptr, nullptr, b_ao };
    dpA.d[1] = dpA.d[0]; dpA.d[2] = dpA.d[0]; dpA.d[3] = dpA.d[0];
    gemm_tc<<<dim3(D_/128, NT_/128), thr, SMEM_DYN>>>(ctxF, wao,
        dpA, NT_, D_, D_, D_, NT_, 0, 0);
    ln_kernel<<<NT_, thr>>>(d_tmp, word, ent, d_ao, 0, gm_ao, bt_ao, d_ao, 0, aoF);

    // FFN1 (+GELU, fp16 out)
    Dest4 dpI;
    dpI.d[0] = { nullptr, intF, nullptr, b_i };
    dpI.d[1] = dpI.d[0]; dpI.d[2] = dpI.d[0]; dpI.d[3] = dpI.d[0];
    gemm_tc<<<dim3(FF_/128, NT_/128), thr, SMEM_DYN>>>(aoF, wi,
        dpI, NT_, FF_, D_, FF_, NT_, 0, 1);

    // FFN2
    Dest4 dpO;
    dpO.d[0] = { d_tmp, nullptr, nullptr, b_o };
    dpO.d[1] = dpO.d[0]; dpO.d[2] = dpO.d[0]; dpO.d[3] = dpO.d[0];
    gemm_tc<<<dim3(D_/128, NT_/128), thr, SMEM_DYN>>>(intF, wo,
        dpO, NT_, D_, FF_, D_, NT_, 0, 0);

    // final LN -> split (word, entity) output
    ln_kernel<<<NT_, thr>>>(d_tmp, nullptr, nullptr, d_ao, 1, gm_o, bt_o,
                            (float*)d_out, 1, nullptr);
}

// round 11
// speedup vs baseline: 2.6101x; 1.0151x over previous
#include <cuda_runtime.h>
#include <cuda_fp16.h>
#include <stdint.h>
#include <math.h>

// Shapes (fixed for this problem)
#define B_  16
#define S_  512
#define E_  128
#define T_  640      // S_ + E_
#define D_  768
#define H_  12
#define DH_ 64
#define FF_ 3072
#define NT_ (B_*T_) // 10240

typedef unsigned int       u32;
typedef unsigned long long u64;

// ---------------- scratch (__device__ globals) ------------------------------
__device__ float g_ao [(size_t)NT_*D_];
__device__ float g_tmp[(size_t)NT_*D_];

__device__ half g_word[(size_t)B_*S_*D_];
__device__ half g_ent [(size_t)B_*E_*D_];
__device__ half g_q1h[(size_t)NT_*D_], g_q1l[(size_t)NT_*D_];
__device__ half g_q2h[(size_t)NT_*D_], g_q2l[(size_t)NT_*D_];
__device__ half g_kh [(size_t)NT_*D_];
__device__ half g_vh [(size_t)NT_*D_];
__device__ half g_ctx[(size_t)NT_*D_];
__device__ half g_aoh[(size_t)NT_*D_];
__device__ half g_int[(size_t)NT_*FF_];

// packed fp16 weights ([N,K] row-major)
__device__ half g_wpw[4*D_*D_];   // word: q | w2e | k | v
__device__ half g_wpe[4*D_*D_];   // ent:  e2w | e2e | k | v
__device__ half g_wao[D_*D_];
__device__ half g_wi [FF_*D_];
__device__ half g_wo [D_*FF_];

struct DestPack { float* y; half* yh; half* yl; const float* bias; };
struct Dest4 { DestPack d[4]; };
struct WBatch9 { const float* src[9]; half* dst[9]; };

// ---------------- PTX helpers ----------------------------------------------
__device__ __forceinline__ u32 smem_u32(const void* p) {
    u32 a;
    asm("{ .reg .u64 t; cvta.to.shared.u64 t, %1; cvt.u32.u64 %0, t; }" : "=r"(a) : "l"(p));
    return a;
}
__device__ __forceinline__ void cpa16(u32 s, const void* g) {
    asm volatile("cp.async.cg.shared.global [%0], [%1], 16;" :: "r"(s), "l"(g));
}
__device__ __forceinline__ void ldsm4(u32 addr, u32& r0, u32& r1, u32& r2, u32& r3) {
    asm volatile("ldmatrix.sync.aligned.m8n8.x4.shared.b16 {%0,%1,%2,%3}, [%4];"
                 : "=r"(r0), "=r"(r1), "=r"(r2), "=r"(r3) : "r"(addr));
}
__device__ __forceinline__ void ldsm4t(u32 addr, u32& r0, u32& r1, u32& r2, u32& r3) {
    asm volatile("ldmatrix.sync.aligned.m8n8.x4.trans.shared.b16 {%0,%1,%2,%3}, [%4];"
                 : "=r"(r0), "=r"(r1), "=r"(r2), "=r"(r3) : "r"(addr));
}
__device__ __forceinline__ void mma_f16(float* c, const u32* a, u32 b0, u32 b1) {
    asm volatile(
        "mma.sync.aligned.m16n8k16.row.col.f32.f16.f16.f32 "
        "{%0,%1,%2,%3}, {%4,%5,%6,%7}, {%8,%9}, {%0,%1,%2,%3};"
        : "+f"(c[0]), "+f"(c[1]), "+f"(c[2]), "+f"(c[3])
        : "r"(a[0]), "r"(a[1]), "r"(a[2]), "r"(a[3]), "r"(b0), "r"(b1));
}
__device__ __forceinline__ float fexp(float x) {
    x = fmaxf(x, -80.f);
    float y = x * 1.4426950408889634f;
    int n = __float2int_rn(y);
    float f = y - (float)n;
    float p = 1.33336e-3f;
    p = fmaf(p, f, 9.61813e-3f);
    p = fmaf(p, f, 5.5504109e-2f);
    p = fmaf(p, f, 2.4022651e-1f);
    p = fmaf(p, f, 6.9314718e-1f);
    p = fmaf(p, f, 1.0f);
    return p * __int_as_float((n + 127) << 23);
}
__device__ __forceinline__ u32 pack_h2(float a, float b) {
    __half2 t = __floats2half2_rn(a, b);
    return *(u32*)&t;
}
__device__ __forceinline__ float h_lo(float v) {
    return v - __half2float(__float2half_rn(v));
}

// ---------------- batched 768x768 weight transpose -> fp16 -------------------
__global__ __launch_bounds__(256)
void wconv9(WBatch9 wb)
{
    __shared__ float t[32][33];
    const float* W = wb.src[blockIdx.z];
    half* Wt = wb.dst[blockIdx.z];
    const int n0 = blockIdx.x * 32, k0 = blockIdx.y * 32;
    const int tx = threadIdx.x & 31, ty = threadIdx.x >> 5;
#pragma unroll
    for (int i = 0; i < 4; i++)
        t[ty + i*8][tx] = W[(size_t)(k0 + ty + i*8) * D_ + n0 + tx];
    __syncthreads();
#pragma unroll
    for (int i = 0; i < 4; i++)
        Wt[(size_t)(n0 + ty + i*8) * D_ + k0 + tx] = __float2half_rn(t[tx][ty + i*8]);
}

// ---------------- generic weight transpose -> fp16 ---------------------------
__global__ __launch_bounds__(256)
void wconv(const float* __restrict__ W, half* __restrict__ Wt, int K, int N)
{
    __shared__ float t[32][33];
    const int n0 = blockIdx.x * 32, k0 = blockIdx.y * 32;
    const int tx = threadIdx.x & 31, ty = threadIdx.x >> 5;
#pragma unroll
    for (int i = 0; i < 4; i++)
        t[ty + i*8][tx] = W[(size_t)(k0 + ty + i*8) * N + n0 + tx];
    __syncthreads();
#pragma unroll
    for (int i = 0; i < 4; i++)
        Wt[(size_t)(n0 + ty + i*8) * K + k0 + tx] = __float2half_rn(t[tx][ty + i*8]);
}

// ---------------- activation convert (fp16 single) ---------------------------
__global__ __launch_bounds__(256)
void aconv(const float* __restrict__ x, half* __restrict__ h)
{
    size_t i = (size_t)blockIdx.x * 256 + threadIdx.x;
    h[i] = __float2half_rn(x[i]);
}

// ---------------- fp16 GEMM (128x128 CTA, 32x64 warp, 2 CTAs/SM) -------------
#define BK_     32
#define TILE_BY (128*80)              // 10240 B per tile
#define STG_BY  (2*TILE_BY)           // 20480 (A, B)
#define SMEM_DYN (3*STG_BY)           // 61440

__global__ __launch_bounds__(256, 2)
void gemm_tc(const half* __restrict__ A, const half* __restrict__ Bt,
             Dest4 dp, int M, int N, int K, int nsplit, int seg, int rowoff, int act)
{
    extern __shared__ char smem[];
    const u32 sb = smem_u32(smem);
    const int tid  = threadIdx.x;
    const int lane = tid & 31;
    const int wid  = tid >> 5;
    const int wm   = wid >> 1;
    const int wn   = wid & 1;
    const int n0 = blockIdx.x * 128;
    const int m0 = blockIdx.y * 128;
    const int nk = K / BK_;

    const half* srcs[2] = { A + (size_t)m0 * K, Bt + (size_t)n0 * K };

    auto load_chunk = [&](int s, int kc) {
        const int k0c = kc * BK_;
#pragma unroll
        for (int i = 0; i < 4; i++) {
            int c   = tid + i * 256;
            int t   = c >> 9;
            int cc  = c & 511;
            int r   = cc >> 2;
            int c16 = cc & 3;
            cpa16(sb + (u32)s * STG_BY + (u32)t * TILE_BY + (u32)(r * 80 + c16 * 16),
                  srcs[t] + k0c + (size_t)r * K + c16 * 8);
        }
        asm volatile("cp.async.commit_group;" ::: "memory");
    };

    float acc[2][8][4];
#pragma unroll
    for (int mt = 0; mt < 2; mt++)
#pragma unroll
        for (int nt = 0; nt < 8; nt++)
#pragma unroll
            for (int j = 0; j < 4; j++) acc[mt][nt][j] = 0.f;

    const u32 frag_row = (u32)(lane & 15);
    const u32 frag_col = (u32)((lane >> 4) << 4);

    load_chunk(0, 0);
    load_chunk(1, 1);

    for (int kc = 0; kc < nk; kc++) {
        const int s = kc % 3;
        if (kc + 2 < nk) {
            load_chunk((kc + 2) % 3, kc + 2);
            asm volatile("cp.async.wait_group 2;" ::: "memory");
        } else if (kc + 1 < nk) {
            asm volatile("cp.async.wait_group 1;" ::: "memory");
        } else {
            asm volatile("cp.async.wait_group 0;" ::: "memory");
        }
        __syncthreads();

        const u32 stg = sb + (u32)s * STG_BY;
        const u32 aBase = stg;
        const u32 bBase = stg + TILE_BY;

#pragma unroll
        for (int ks = 0; ks < 2; ks++) {
            const u32 kByte = (u32)(ks * 32) + frag_col;
            u32 a[2][4], bb[4][4];
#pragma unroll
            for (int mt = 0; mt < 2; mt++) {
                u32 ro = (u32)(wm * 32 + mt * 16) + frag_row;
                ldsm4(aBase + ro * 80 + kByte, a[mt][0], a[mt][1], a[mt][2], a[mt][3]);
            }
#pragma unroll
            for (int np = 0; np < 4; np++) {
                u32 ro = (u32)(wn * 64 + np * 16) + frag_row;
                ldsm4(bBase + ro * 80 + kByte, bb[np][0], bb[np][1], bb[np][2], bb[np][3]);
            }
#pragma unroll
            for (int mt = 0; mt < 2; mt++)
#pragma unroll
                for (int nt = 0; nt < 8; nt++) {
                    int np = nt >> 1, sel = nt & 1;
                    mma_f16(acc[mt][nt], a[mt], bb[np][sel], bb[np][sel + 2]);
                }
        }
        __syncthreads();
    }

    const int di = n0 / nsplit;
    float* Y  = dp.d[di].y;
    half* Yh  = dp.d[di].yh;
    half* Yl  = dp.d[di].yl;
    const float* bias = dp.d[di].bias;
    const int ncol_off = di * nsplit;

#pragma unroll
    for (int mt = 0; mt < 2; mt++) {
#pragma unroll
        for (int half_ = 0; half_ < 2; half_++) {
            int mlog = m0 + wm * 32 + mt * 16 + (lane >> 2) + half_ * 8;
            size_t phys = (size_t)(mlog / seg) * T_ + (mlog % seg) + rowoff;
#pragma unroll
            for (int nt = 0; nt < 8; nt++) {
                int col = n0 + wn * 64 + nt * 8 + (lane & 3) * 2 - ncol_off;
                float v0 = acc[mt][nt][half_ * 2 + 0] + bias[col + 0];
                float v1 = acc[mt][nt][half_ * 2 + 1] + bias[col + 1];
                if (act == 0) {
                    *(float2*)(Y + phys * (size_t)nsplit + col) = make_float2(v0, v1);
                } else {
                    if (act == 1) {
                        v0 = 0.5f * v0 * (1.0f + erff(v0 * 0.70710678f));
                        v1 = 0.5f * v1 * (1.0f + erff(v1 * 0.70710678f));
                    }
                    *(u32*)(Yh + phys * (size_t)nsplit + col) = pack_h2(v0, v1);
                    if (Yl)
                        *(u32*)(Yl + phys * (size_t)nsplit + col) = pack_h2(h_lo(v0), h_lo(v1));
                }
            }
        }
    }
}

// ---------------- fp16 flash attention (unchanged) ---------------------------
#define QT_BY   (128*144)
#define A_Q1H   0
#define A_Q1L   (1*QT_BY)
#define A_Q2H   (2*QT_BY)
#define A_Q2L   (3*QT_BY)
#define A_K     (4*QT_BY)
#define A_V     (5*QT_BY)
#define A_MS    (6*QT_BY)
#define ATT_SMEM (6*QT_BY + 512)     // 111104

__global__ __launch_bounds__(256, 1)
void attn_tc(const half* __restrict__ q1h, const half* __restrict__ q1l,
             const half* __restrict__ q2h, const half* __restrict__ q2l,
             const half* __restrict__ kh,  const half* __restrict__ vh,
             const float* __restrict__ mask,
             half* __restrict__ ctxH)
{
    extern __shared__ char smem[];
    const u32 sb = smem_u32(smem);
    float* maskS = (float*)(smem + A_MS);

    const int b  = blockIdx.z;
    const int h  = blockIdx.y;
    const int q0 = blockIdx.x * 128;
    const int tid  = threadIdx.x;
    const int lane = tid & 31;
    const int w    = tid >> 5;

    const u32 frag_row = (u32)(lane & 15);
    const u32 frag_col = (u32)((lane >> 4) << 4);

    {
        const half* srcQ[4] = { q1h, q1l, q2h, q2l };
#pragma unroll
        for (int i = 0; i < 16; i++) {
            int idx = tid + i * 256;
            int arr = idx >> 10;
            int rr  = (idx >> 3) & 127;
            int ch  = idx & 7;
            cpa16(sb + (u32)(arr * QT_BY + rr * 144 + ch * 16),
                  srcQ[arr] + (size_t)(b * T_ + q0 + rr) * D_ + h * DH_ + ch * 8);
        }
        asm volatile("cp.async.commit_group;" ::: "memory");
    }

    float Oa[8][4];
#pragma unroll
    for (int od = 0; od < 8; od++)
#pragma unroll
        for (int j = 0; j < 4; j++) Oa[od][j] = 0.f;
    float m0 = -1e30f, m1 = -1e30f, l0 = 0.f, l1 = 0.f;

    for (int kt = 0; kt < 5; kt++) {
        __syncthreads();
        {
            const half* srcT[2] = { kh, vh };
#pragma unroll
            for (int i = 0; i < 8; i++) {
                int idx = tid + i * 256;
                int arr = idx >> 10;
                int rr  = (idx >> 3) & 127;
                int ch  = idx & 7;
                cpa16(sb + (u32)(A_K + arr * QT_BY + rr * 144 + ch * 16),
                      srcT[arr] + (size_t)(b * T_ + kt * 128 + rr) * D_ + h * DH_ + ch * 8);
            }
            if (tid < 128) maskS[tid] = mask[b * T_ + kt * 128 + tid];
            asm volatile("cp.async.commit_group;" ::: "memory");
            asm volatile("cp.async.wait_group 0;" ::: "memory");
        }
        __syncthreads();

        const u32 qbh = sb + (u32)((kt < 4) ? A_Q1H : A_Q2H);
        const u32 qbl = qbh + QT_BY;

        float sc_[16][4];
#pragma unroll
        for (int nt = 0; nt < 16; nt++)
#pragma unroll
            for (int j = 0; j < 4; j++) sc_[nt][j] = 0.f;

#pragma unroll
        for (int ks = 0; ks < 4; ks++) {
            const u32 kByte = (u32)(ks * 32) + frag_col;
            u32 ah[4], al[4], bh[8][4];
            u32 ro = (u32)(w * 16) + frag_row;
            ldsm4(qbh + ro * 144 + kByte, ah[0], ah[1], ah[2], ah[3]);
            ldsm4(qbl + ro * 144 + kByte, al[0], al[1], al[2], al[3]);
#pragma unroll
            for (int np = 0; np < 8; np++) {
                u32 kr = (u32)(np * 16) + frag_row;
                ldsm4(sb + A_K + kr * 144 + kByte, bh[np][0], bh[np][1], bh[np][2], bh[np][3]);
            }
#pragma unroll
            for (int nt = 0; nt < 16; nt++) {
                int np = nt >> 1, sel = nt & 1;
                u32 b0 = bh[np][sel], b1 = bh[np][sel + 2];
                mma_f16(sc_[nt], ah, b0, b1);
                mma_f16(sc_[nt], al, b0, b1);
            }
        }

        float rmax0 = -1e30f, rmax1 = -1e30f;
#pragma unroll
        for (int nt = 0; nt < 16; nt++) {
            int cbase = nt * 8 + (lane & 3) * 2;
            float mk0 = maskS[cbase], mk1 = maskS[cbase + 1];
            sc_[nt][0] = fmaf(sc_[nt][0], 0.125f, mk0);
            sc_[nt][1] = fmaf(sc_[nt][1], 0.125f, mk1);
            sc_[nt][2] = fmaf(sc_[nt][2], 0.125f, mk0);
            sc_[nt][3] = fmaf(sc_[nt][3], 0.125f, mk1);
            rmax0 = fmaxf(rmax0, fmaxf(sc_[nt][0], sc_[nt][1]));
            rmax1 = fmaxf(rmax1, fmaxf(sc_[nt][2], sc_[nt][3]));
        }
        rmax0 = fmaxf(rmax0, __shfl_xor_sync(0xffffffffu, rmax0, 1));
        rmax0 = fmaxf(rmax0, __shfl_xor_sync(0xffffffffu, rmax0, 2));
        rmax1 = fmaxf(rmax1, __shfl_xor_sync(0xffffffffu, rmax1, 1));
        rmax1 = fmaxf(rmax1, __shfl_xor_sync(0xffffffffu, rmax1, 2));

        float mn0 = fmaxf(m0, rmax0), mn1 = fmaxf(m1, rmax1);
        float f0 = fexp(m0 - mn0), f1 = fexp(m1 - mn1);
        float rs0 = 0.f, rs1 = 0.f;
#pragma unroll
        for (int nt = 0; nt < 16; nt++) {
            sc_[nt][0] = fexp(sc_[nt][0] - mn0);
            sc_[nt][1] = fexp(sc_[nt][1] - mn0);
            sc_[nt][2] = fexp(sc_[nt][2] - mn1);
            sc_[nt][3] = fexp(sc_[nt][3] - mn1);
            rs0 += sc_[nt][0] + sc_[nt][1];
            rs1 += sc_[nt][2] + sc_[nt][3];
        }
        rs0 += __shfl_xor_sync(0xffffffffu, rs0, 1);
        rs0 += __shfl_xor_sync(0xffffffffu, rs0, 2);
        rs1 += __shfl_xor_sync(0xffffffffu, rs1, 1);
        rs1 += __shfl_xor_sync(0xffffffffu, rs1, 2);
        l0 = l0 * f0 + rs0;
        l1 = l1 * f1 + rs1;
        m0 = mn0; m1 = mn1;
#pragma unroll
        for (int od = 0; od < 8; od++) {
            Oa[od][0] *= f0; Oa[od][1] *= f0;
            Oa[od][2] *= f1; Oa[od][3] *= f1;
        }

#pragma unroll
        for (int ks2 = 0; ks2 < 8; ks2++) {
            float p00 = sc_[2*ks2][0],   p01 = sc_[2*ks2][1];
            float p02 = sc_[2*ks2][2],   p03 = sc_[2*ks2][3];
            float p10 = sc_[2*ks2+1][0], p11 = sc_[2*ks2+1][1];
            float p12 = sc_[2*ks2+1][2], p13 = sc_[2*ks2+1][3];
            u32 aPh[4], aPl[4];
            aPh[0] = pack_h2(p00, p01);
            aPh[1] = pack_h2(p02, p03);
            aPh[2] = pack_h2(p10, p11);
            aPh[3] = pack_h2(p12, p13);
            aPl[0] = pack_h2(h_lo(p00), h_lo(p01));
            aPl[1] = pack_h2(h_lo(p02), h_lo(p03));
            aPl[2] = pack_h2(h_lo(p10), h_lo(p11));
            aPl[3] = pack_h2(h_lo(p12), h_lo(p13));

            const u32 vr = (u32)(ks2 * 16) + frag_row;
#pragma unroll
            for (int nd = 0; nd < 4; nd++) {
                const u32 cByte = (u32)(nd * 32) + frag_col;
                u32 v0, v1, v2, v3;
                ldsm4t(sb + A_V + vr * 144 + cByte, v0, v1, v2, v3);
                int od0 = nd * 2, od1 = nd * 2 + 1;
                mma_f16(Oa[od0], aPh, v0, v1);
                mma_f16(Oa[od0], aPl, v0, v1);
                mma_f16(Oa[od1], aPh, v2, v3);
                mma_f16(Oa[od1], aPl, v2, v3);
            }
        }
    }

    float inv0 = 1.f / l0, inv1 = 1.f / l1;
    int qa = q0 + w * 16 + (lane >> 2);
    int qb = qa + 8;
    size_t baseA = (size_t)(b * T_ + qa) * D_ + h * DH_;
    size_t baseB = (size_t)(b * T_ + qb) * D_ + h * DH_;
#pragma unroll
    for (int od = 0; od < 8; od++) {
        int col = od * 8 + (lane & 3) * 2;
        *(u32*)(ctxH + baseA + col) = pack_h2(Oa[od][0] * inv0, Oa[od][1] * inv0);
        *(u32*)(ctxH + baseB + col) = pack_h2(Oa[od][2] * inv1, Oa[od][3] * inv1);
    }
}

// ---------------- residual + LayerNorm ---------------------------------------
__global__ __launch_bounds__(256)
void ln_kernel(const float* __restrict__ raw,
               const float* __restrict__ rw, const float* __restrict__ re,
               const float* __restrict__ rfull, int use_full,
               const float* __restrict__ gm, const float* __restrict__ bt,
               float* __restrict__ out, int final_mode,
               half* __restrict__ outH)
{
    const int row = blockIdx.x;
    const int b = row / T_, t = row % T_;
    const float* rp = use_full
        ? rfull + (size_t)row * D_
        : (t < S_ ? rw + ((size_t)(b * S_ + t)) * D_
                  : re + ((size_t)(b * E_ + t - S_)) * D_);
    const float* x = raw + (size_t)row * D_;

    float vv[3];
    float s = 0.f, sq = 0.f;
#pragma unroll
    for (int i = 0; i < 3; i++) {
        int c = threadIdx.x + i * 256;
        float val = x[c] + rp[c];
        vv[i] = val;
        s += val;
        sq += val * val;
    }
    const int lane = threadIdx.x & 31, w = threadIdx.x >> 5;
#pragma unroll
    for (int o = 16; o; o >>= 1) {
        s  += __shfl_xor_sync(0xffffffffu, s,  o);
        sq += __shfl_xor_sync(0xffffffffu, sq, o);
    }
    __shared__ float ws[8], wq[8];
    __shared__ float sm, sv;
    if (lane == 0) { ws[w] = s; wq[w] = sq; }
    __syncthreads();
    if (threadIdx.x == 0) {
        float ts = 0.f, tq = 0.f;
#pragma unroll
        for (int i = 0; i < 8; i++) { ts += ws[i]; tq += wq[i]; }
        float mean = ts * (1.f / D_);
        sm = mean;
        sv = rsqrtf(tq * (1.f / D_) - mean * mean + 1e-12f);
    }
    __syncthreads();
    const float mean = sm, inv = sv;

    float* o = final_mode
        ? (t < S_ ? out + ((size_t)(b * S_ + t)) * D_
                  : out + (size_t)B_ * S_ * D_ + ((size_t)(b * E_ + t - S_)) * D_)
        : out + (size_t)row * D_;
#pragma unroll
    for (int i = 0; i < 3; i++) {
        int c = threadIdx.x + i * 256;
        float y = (vv[i] - mean) * inv * gm[c] + bt[c];
        o[c] = y;
        if (outH)
            outH[(size_t)row * D_ + c] = __float2half_rn(y);
    }
}

// ---------------- host -------------------------------------------------------
extern "C" void kernel_launch(void* const* d_in, const int* in_sizes, int n_in,
                              void* d_out, int out_size)
{
    const float* word  = (const float*)d_in[0];
    const float* ent   = (const float*)d_in[1];
    const float* mask  = (const float*)d_in[2];
    const float* W_q   = (const float*)d_in[3],  *b_q    = (const float*)d_in[4];
    const float* W_k   = (const float*)d_in[5],  *b_k    = (const float*)d_in[6];
    const float* W_v   = (const float*)d_in[7],  *b_v    = (const float*)d_in[8];
    const float* W_w2e = (const float*)d_in[9],  *b_w2e  = (const float*)d_in[10];
    const float* W_e2w = (const float*)d_in[11], *b_e2w  = (const float*)d_in[12];
    const float* W_e2e = (const float*)d_in[13], *b_e2e  = (const float*)d_in[14];
    const float* W_ao  = (const float*)d_in[15], *b_ao   = (const float*)d_in[16];
    const float* gm_ao = (const float*)d_in[17], *bt_ao  = (const float*)d_in[18];
    const float* W_i   = (const float*)d_in[19], *b_i    = (const float*)d_in[20];
    const float* W_o   = (const float*)d_in[21], *b_o    = (const float*)d_in[22];
    const float* gm_o  = (const float*)d_in[23], *bt_o   = (const float*)d_in[24];

    void* p;
    cudaGetSymbolAddress(&p, g_ao);    float* d_ao  = (float*)p;
    cudaGetSymbolAddress(&p, g_tmp);   float* d_tmp = (float*)p;

    half *wordF,*entF,*q1H,*q1L,*q2H,*q2L,*kH,*vH,*ctxF,*aoF,*intF;
    cudaGetSymbolAddress(&p, g_word); wordF = (half*)p;
    cudaGetSymbolAddress(&p, g_ent);  entF  = (half*)p;
    cudaGetSymbolAddress(&p, g_q1h);  q1H   = (half*)p;
    cudaGetSymbolAddress(&p, g_q1l);  q1L   = (half*)p;
    cudaGetSymbolAddress(&p, g_q2h);  q2H   = (half*)p;
    cudaGetSymbolAddress(&p, g_q2l);  q2L   = (half*)p;
    cudaGetSymbolAddress(&p, g_kh);   kH    = (half*)p;
    cudaGetSymbolAddress(&p, g_vh);   vH    = (half*)p;
    cudaGetSymbolAddress(&p, g_ctx);  ctxF  = (half*)p;
    cudaGetSymbolAddress(&p, g_aoh);  aoF   = (half*)p;
    cudaGetSymbolAddress(&p, g_int);  intF  = (half*)p;

    half *wpw,*wpe,*wao,*wi,*wo;
    cudaGetSymbolAddress(&p, g_wpw); wpw = (half*)p;
    cudaGetSymbolAddress(&p, g_wpe); wpe = (half*)p;
    cudaGetSymbolAddress(&p, g_wao); wao = (half*)p;
    cudaGetSymbolAddress(&p, g_wi);  wi  = (half*)p;
    cudaGetSymbolAddress(&p, g_wo);  wo  = (half*)p;

    cudaFuncSetAttribute(gemm_tc, cudaFuncAttributeMaxDynamicSharedMemorySize, SMEM_DYN);
    cudaFuncSetAttribute(attn_tc, cudaFuncAttributeMaxDynamicSharedMemorySize, ATT_SMEM);

    const dim3 thr(256);
    const int MW = B_ * S_;
    const int ME = B_ * E_;
    const size_t WSLICE = (size_t)D_ * D_;

    // batched 768x768 weight conversions (9 in one launch)
    WBatch9 wb;
    wb.src[0] = W_q;   wb.dst[0] = wpw + 0*WSLICE;
    wb.src[1] = W_w2e; wb.dst[1] = wpw + 1*WSLICE;
    wb.src[2] = W_k;   wb.dst[2] = wpw + 2*WSLICE;
    wb.src[3] = W_v;   wb.dst[3] = wpw + 3*WSLICE;
    wb.src[4] = W_e2w; wb.dst[4] = wpe + 0*WSLICE;
    wb.src[5] = W_e2e; wb.dst[5] = wpe + 1*WSLICE;
    wb.src[6] = W_k;   wb.dst[6] = wpe + 2*WSLICE;
    wb.src[7] = W_v;   wb.dst[7] = wpe + 3*WSLICE;
    wb.src[8] = W_ao;  wb.dst[8] = wao;
    wconv9<<<dim3(D_/32, D_/32, 9), thr>>>(wb);
    wconv<<<dim3(FF_/32, D_/32),  thr>>>(W_i, wi, D_,  FF_);
    wconv<<<dim3(D_/32,  FF_/32), thr>>>(W_o, wo, FF_, D_);

    aconv<<<(unsigned)((size_t)MW * D_ / 256), thr>>>(word, wordF);
    aconv<<<(unsigned)((size_t)ME * D_ / 256), thr>>>(ent,  entF);

    // packed projections (word + entity), interleaved into [B,T,D]
    Dest4 dpW;
    dpW.d[0] = { nullptr, q1H, q1L,     b_q   };
    dpW.d[1] = { nullptr, q2H, q2L,     b_w2e };
    dpW.d[2] = { nullptr, kH,  nullptr, b_k   };
    dpW.d[3] = { nullptr, vH,  nullptr, b_v   };
    gemm_tc<<<dim3(4*D_/128, MW/128), thr, SMEM_DYN>>>(wordF, wpw,
        dpW, MW, 4*D_, D_, D_, S_, 0, 2);

    Dest4 dpE;
    dpE.d[0] = { nullptr, q1H, q1L,     b_e2w };
    dpE.d[1] = { nullptr, q2H, q2L,     b_e2e };
    dpE.d[2] = { nullptr, kH,  nullptr, b_k   };
    dpE.d[3] = { nullptr, vH,  nullptr, b_v   };
    gemm_tc<<<dim3(4*D_/128, ME/128), thr, SMEM_DYN>>>(entF, wpe,
        dpE, ME, 4*D_, D_, D_, E_, S_, 2);

    // attention -> fp16 ctx
    attn_tc<<<dim3(T_/128, H_, B_), thr, ATT_SMEM>>>(q1H, q1L, q2H, q2L, kH, vH,
                                                     mask, ctxF);

    // AO projection + LN (LN emits fp16 ao for FFN1)
    Dest4 dpA;
    dpA.d[0] = { d_tmp, nullptr, nullptr, b_ao };
    dpA.d[1] = dpA.d[0]; dpA.d[2] = dpA.d[0]; dpA.d[3] = dpA.d[0];
    gemm_tc<<<dim3(D_/128, NT_/128), thr, SMEM_DYN>>>(ctxF, wao,
        dpA, NT_, D_, D_, D_, NT_, 0, 0);
    ln_kernel<<<NT_, thr>>>(d_tmp, word, ent, d_ao, 0, gm_ao, bt_ao, d_ao, 0, aoF);

    // FFN1 (+GELU, fp16 out)
    Dest4 dpI;
    dpI.d[0] = { nullptr, intF, nullptr, b_i };
    dpI.d[1] = dpI.d[0]; dpI.d[2] = dpI.d[0]; dpI.d[3] = dpI.d[0];
    gemm_tc<<<dim3(FF_/128, NT_/128), thr, SMEM_DYN>>>(aoF, wi,
        dpI, NT_, FF_, D_, FF_, NT_, 0, 1);

    // FFN2
    Dest4 dpO;
    dpO.d[0] = { d_tmp, nullptr, nullptr, b_o };
    dpO.d[1] = dpO.d[0]; dpO.d[2] = dpO.d[0]; dpO.d[3] = dpO.d[0];
    gemm_tc<<<dim3(D_/128, NT_/128), thr, SMEM_DYN>>>(intF, wo,
        dpO, NT_, D_, FF_, D_, NT_, 0, 0);

    // final LN -> split (word, entity) output
    ln_kernel<<<NT_, thr>>>(d_tmp, nullptr, nullptr, d_ao, 1, gm_o, bt_o,
                            (float*)d_out, 1, nullptr);
}

// round 12
// speedup vs baseline: 2.7403x; 1.0499x over previous
#include <cuda_runtime.h>
#include <cuda_fp16.h>
#include <stdint.h>
#include <math.h>

// Shapes (fixed for this problem)
#define B_  16
#define S_  512
#define E_  128
#define T_  640      // S_ + E_
#define D_  768
#define H_  12
#define DH_ 64
#define FF_ 3072
#define NT_ (B_*T_) // 10240

typedef unsigned int       u32;
typedef unsigned long long u64;

// ---------------- scratch (__device__ globals) ------------------------------
__device__ float g_ao [(size_t)NT_*D_];
__device__ float g_tmp[(size_t)NT_*D_];

__device__ half g_word[(size_t)B_*S_*D_];
__device__ half g_ent [(size_t)B_*E_*D_];
__device__ half g_q1[(size_t)NT_*D_];
__device__ half g_q2[(size_t)NT_*D_];
__device__ half g_kh [(size_t)NT_*D_];
__device__ half g_vh [(size_t)NT_*D_];
__device__ half g_ctx[(size_t)NT_*D_];
__device__ half g_aoh[(size_t)NT_*D_];
__device__ half g_int[(size_t)NT_*FF_];

// packed fp16 weights ([N,K] row-major)
__device__ half g_wpw[4*D_*D_];   // word: q | w2e | k | v
__device__ half g_wpe[4*D_*D_];   // ent:  e2w | e2e | k | v
__device__ half g_wao[D_*D_];
__device__ half g_wi [FF_*D_];
__device__ half g_wo [D_*FF_];

struct DestPack { float* y; half* yh; half* yl; const float* bias; };
struct Dest4 { DestPack d[4]; };
struct WBatch9 { const float* src[9]; half* dst[9]; };

// ---------------- PTX helpers ----------------------------------------------
__device__ __forceinline__ u32 smem_u32(const void* p) {
    u32 a;
    asm("{ .reg .u64 t; cvta.to.shared.u64 t, %1; cvt.u32.u64 %0, t; }" : "=r"(a) : "l"(p));
    return a;
}
__device__ __forceinline__ void cpa16(u32 s, const void* g) {
    asm volatile("cp.async.cg.shared.global [%0], [%1], 16;" :: "r"(s), "l"(g));
}
__device__ __forceinline__ void ldsm4(u32 addr, u32& r0, u32& r1, u32& r2, u32& r3) {
    asm volatile("ldmatrix.sync.aligned.m8n8.x4.shared.b16 {%0,%1,%2,%3}, [%4];"
                 : "=r"(r0), "=r"(r1), "=r"(r2), "=r"(r3) : "r"(addr));
}
__device__ __forceinline__ void ldsm4t(u32 addr, u32& r0, u32& r1, u32& r2, u32& r3) {
    asm volatile("ldmatrix.sync.aligned.m8n8.x4.trans.shared.b16 {%0,%1,%2,%3}, [%4];"
                 : "=r"(r0), "=r"(r1), "=r"(r2), "=r"(r3) : "r"(addr));
}
__device__ __forceinline__ void mma_f16(float* c, const u32* a, u32 b0, u32 b1) {
    asm volatile(
        "mma.sync.aligned.m16n8k16.row.col.f32.f16.f16.f32 "
        "{%0,%1,%2,%3}, {%4,%5,%6,%7}, {%8,%9}, {%0,%1,%2,%3};"
        : "+f"(c[0]), "+f"(c[1]), "+f"(c[2]), "+f"(c[3])
        : "r"(a[0]), "r"(a[1]), "r"(a[2]), "r"(a[3]), "r"(b0), "r"(b1));
}
__device__ __forceinline__ float fexp(float x) {
    x = fmaxf(x, -80.f);
    float y = x * 1.4426950408889634f;
    int n = __float2int_rn(y);
    float f = y - (float)n;
    float p = 1.33336e-3f;
    p = fmaf(p, f, 9.61813e-3f);
    p = fmaf(p, f, 5.5504109e-2f);
    p = fmaf(p, f, 2.4022651e-1f);
    p = fmaf(p, f, 6.9314718e-1f);
    p = fmaf(p, f, 1.0f);
    return p * __int_as_float((n + 127) << 23);
}
__device__ __forceinline__ u32 pack_h2(float a, float b) {
    __half2 t = __floats2half2_rn(a, b);
    return *(u32*)&t;
}
__device__ __forceinline__ float h_lo(float v) {
    return v - __half2float(__float2half_rn(v));
}

// ---------------- batched 768x768 weight transpose -> fp16 -------------------
__global__ __launch_bounds__(256)
void wconv9(WBatch9 wb)
{
    __shared__ float t[32][33];
    const float* W = wb.src[blockIdx.z];
    half* Wt = wb.dst[blockIdx.z];
    const int n0 = blockIdx.x * 32, k0 = blockIdx.y * 32;
    const int tx = threadIdx.x & 31, ty = threadIdx.x >> 5;
#pragma unroll
    for (int i = 0; i < 4; i++)
        t[ty + i*8][tx] = W[(size_t)(k0 + ty + i*8) * D_ + n0 + tx];
    __syncthreads();
#pragma unroll
    for (int i = 0; i < 4; i++)
        Wt[(size_t)(n0 + ty + i*8) * D_ + k0 + tx] = __float2half_rn(t[tx][ty + i*8]);
}

// ---------------- generic weight transpose -> fp16 ---------------------------
__global__ __launch_bounds__(256)
void wconv(const float* __restrict__ W, half* __restrict__ Wt, int K, int N)
{
    __shared__ float t[32][33];
    const int n0 = blockIdx.x * 32, k0 = blockIdx.y * 32;
    const int tx = threadIdx.x & 31, ty = threadIdx.x >> 5;
#pragma unroll
    for (int i = 0; i < 4; i++)
        t[ty + i*8][tx] = W[(size_t)(k0 + ty + i*8) * N + n0 + tx];
    __syncthreads();
#pragma unroll
    for (int i = 0; i < 4; i++)
        Wt[(size_t)(n0 + ty + i*8) * K + k0 + tx] = __float2half_rn(t[tx][ty + i*8]);
}

// ---------------- activation convert (fp16 single) ---------------------------
__global__ __launch_bounds__(256)
void aconv(const float* __restrict__ x, half* __restrict__ h)
{
    size_t i = (size_t)blockIdx.x * 256 + threadIdx.x;
    h[i] = __float2half_rn(x[i]);
}

// ---------------- fp16 GEMM (128x128 CTA, 32x64 warp, 2 CTAs/SM) -------------
#define BK_     32
#define TILE_BY (128*80)              // 10240 B per tile
#define STG_BY  (2*TILE_BY)           // 20480 (A, B)
#define SMEM_DYN (3*STG_BY)           // 61440

__global__ __launch_bounds__(256, 2)
void gemm_tc(const half* __restrict__ A, const half* __restrict__ Bt,
             Dest4 dp, int M, int N, int K, int nsplit, int seg, int rowoff, int act)
{
    extern __shared__ char smem[];
    const u32 sb = smem_u32(smem);
    const int tid  = threadIdx.x;
    const int lane = tid & 31;
    const int wid  = tid >> 5;
    const int wm   = wid >> 1;
    const int wn   = wid & 1;
    const int n0 = blockIdx.x * 128;
    const int m0 = blockIdx.y * 128;
    const int nk = K / BK_;

    const half* srcs[2] = { A + (size_t)m0 * K, Bt + (size_t)n0 * K };

    auto load_chunk = [&](int s, int kc) {
        const int k0c = kc * BK_;
#pragma unroll
        for (int i = 0; i < 4; i++) {
            int c   = tid + i * 256;
            int t   = c >> 9;
            int cc  = c & 511;
            int r   = cc >> 2;
            int c16 = cc & 3;
            cpa16(sb + (u32)s * STG_BY + (u32)t * TILE_BY + (u32)(r * 80 + c16 * 16),
                  srcs[t] + k0c + (size_t)r * K + c16 * 8);
        }
        asm volatile("cp.async.commit_group;" ::: "memory");
    };

    float acc[2][8][4];
#pragma unroll
    for (int mt = 0; mt < 2; mt++)
#pragma unroll
        for (int nt = 0; nt < 8; nt++)
#pragma unroll
            for (int j = 0; j < 4; j++) acc[mt][nt][j] = 0.f;

    const u32 frag_row = (u32)(lane & 15);
    const u32 frag_col = (u32)((lane >> 4) << 4);

    load_chunk(0, 0);
    load_chunk(1, 1);

    for (int kc = 0; kc < nk; kc++) {
        const int s = kc % 3;
        if (kc + 2 < nk) {
            load_chunk((kc + 2) % 3, kc + 2);
            asm volatile("cp.async.wait_group 2;" ::: "memory");
        } else if (kc + 1 < nk) {
            asm volatile("cp.async.wait_group 1;" ::: "memory");
        } else {
            asm volatile("cp.async.wait_group 0;" ::: "memory");
        }
        __syncthreads();

        const u32 stg = sb + (u32)s * STG_BY;
        const u32 aBase = stg;
        const u32 bBase = stg + TILE_BY;

#pragma unroll
        for (int ks = 0; ks < 2; ks++) {
            const u32 kByte = (u32)(ks * 32) + frag_col;
            u32 a[2][4], bb[4][4];
#pragma unroll
            for (int mt = 0; mt < 2; mt++) {
                u32 ro = (u32)(wm * 32 + mt * 16) + frag_row;
                ldsm4(aBase + ro * 80 + kByte, a[mt][0], a[mt][1], a[mt][2], a[mt][3]);
            }
#pragma unroll
            for (int np = 0; np < 4; np++) {
                u32 ro = (u32)(wn * 64 + np * 16) + frag_row;
                ldsm4(bBase + ro * 80 + kByte, bb[np][0], bb[np][1], bb[np][2], bb[np][3]);
            }
#pragma unroll
            for (int mt = 0; mt < 2; mt++)
#pragma unroll
                for (int nt = 0; nt < 8; nt++) {
                    int np = nt >> 1, sel = nt & 1;
                    mma_f16(acc[mt][nt], a[mt], bb[np][sel], bb[np][sel + 2]);
                }
        }
        __syncthreads();
    }

    const int di = n0 / nsplit;
    float* Y  = dp.d[di].y;
    half* Yh  = dp.d[di].yh;
    half* Yl  = dp.d[di].yl;
    const float* bias = dp.d[di].bias;
    const int ncol_off = di * nsplit;

#pragma unroll
    for (int mt = 0; mt < 2; mt++) {
#pragma unroll
        for (int half_ = 0; half_ < 2; half_++) {
            int mlog = m0 + wm * 32 + mt * 16 + (lane >> 2) + half_ * 8;
            size_t phys = (size_t)(mlog / seg) * T_ + (mlog % seg) + rowoff;
#pragma unroll
            for (int nt = 0; nt < 8; nt++) {
                int col = n0 + wn * 64 + nt * 8 + (lane & 3) * 2 - ncol_off;
                float v0 = acc[mt][nt][half_ * 2 + 0] + bias[col + 0];
                float v1 = acc[mt][nt][half_ * 2 + 1] + bias[col + 1];
                if (act == 0) {
                    *(float2*)(Y + phys * (size_t)nsplit + col) = make_float2(v0, v1);
                } else {
                    if (act == 1) {
                        v0 = 0.5f * v0 * (1.0f + erff(v0 * 0.70710678f));
                        v1 = 0.5f * v1 * (1.0f + erff(v1 * 0.70710678f));
                    }
                    *(u32*)(Yh + phys * (size_t)nsplit + col) = pack_h2(v0, v1);
                    if (Yl)
                        *(u32*)(Yl + phys * (size_t)nsplit + col) = pack_h2(h_lo(v0), h_lo(v1));
                }
            }
        }
    }
}

// ---------------- fp16 flash attention (single-precision Q and P) ------------
// Tiles: Q1, Q2, K, V = 4 x 128x144B -> 74 KB -> 2 CTAs/SM.
#define QT_BY   (128*144)
#define A_Q1    0
#define A_Q2    (1*QT_BY)
#define A_K     (2*QT_BY)
#define A_V     (3*QT_BY)
#define A_MS    (4*QT_BY)
#define ATT_SMEM (4*QT_BY + 512)     // 74240

__global__ __launch_bounds__(256, 2)
void attn_tc(const half* __restrict__ q1, const half* __restrict__ q2,
             const half* __restrict__ kh,  const half* __restrict__ vh,
             const float* __restrict__ mask,
             half* __restrict__ ctxH)
{
    extern __shared__ char smem[];
    const u32 sb = smem_u32(smem);
    float* maskS = (float*)(smem + A_MS);

    const int b  = blockIdx.z;
    const int h  = blockIdx.y;
    const int q0 = blockIdx.x * 128;
    const int tid  = threadIdx.x;
    const int lane = tid & 31;
    const int w    = tid >> 5;

    const u32 frag_row = (u32)(lane & 15);
    const u32 frag_col = (u32)((lane >> 4) << 4);

    {
        const half* srcQ[2] = { q1, q2 };
#pragma unroll
        for (int i = 0; i < 8; i++) {
            int idx = tid + i * 256;            // 0..2047
            int arr = idx >> 10;
            int rr  = (idx >> 3) & 127;
            int ch  = idx & 7;
            cpa16(sb + (u32)(arr * QT_BY + rr * 144 + ch * 16),
                  srcQ[arr] + (size_t)(b * T_ + q0 + rr) * D_ + h * DH_ + ch * 8);
        }
        asm volatile("cp.async.commit_group;" ::: "memory");
    }

    float Oa[8][4];
#pragma unroll
    for (int od = 0; od < 8; od++)
#pragma unroll
        for (int j = 0; j < 4; j++) Oa[od][j] = 0.f;
    float m0 = -1e30f, m1 = -1e30f, l0 = 0.f, l1 = 0.f;

    for (int kt = 0; kt < 5; kt++) {
        __syncthreads();
        {
            const half* srcT[2] = { kh, vh };
#pragma unroll
            for (int i = 0; i < 8; i++) {
                int idx = tid + i * 256;
                int arr = idx >> 10;
                int rr  = (idx >> 3) & 127;
                int ch  = idx & 7;
                cpa16(sb + (u32)(A_K + arr * QT_BY + rr * 144 + ch * 16),
                      srcT[arr] + (size_t)(b * T_ + kt * 128 + rr) * D_ + h * DH_ + ch * 8);
            }
            if (tid < 128) maskS[tid] = mask[b * T_ + kt * 128 + tid];
            asm volatile("cp.async.commit_group;" ::: "memory");
            asm volatile("cp.async.wait_group 0;" ::: "memory");
        }
        __syncthreads();

        const u32 qb = sb + (u32)((kt < 4) ? A_Q1 : A_Q2);

        float sc_[16][4];
#pragma unroll
        for (int nt = 0; nt < 16; nt++)
#pragma unroll
            for (int j = 0; j < 4; j++) sc_[nt][j] = 0.f;

#pragma unroll
        for (int ks = 0; ks < 4; ks++) {
            const u32 kByte = (u32)(ks * 32) + frag_col;
            u32 a[4], bh[8][4];
            u32 ro = (u32)(w * 16) + frag_row;
            ldsm4(qb + ro * 144 + kByte, a[0], a[1], a[2], a[3]);
#pragma unroll
            for (int np = 0; np < 8; np++) {
                u32 kr = (u32)(np * 16) + frag_row;
                ldsm4(sb + A_K + kr * 144 + kByte, bh[np][0], bh[np][1], bh[np][2], bh[np][3]);
            }
#pragma unroll
            for (int nt = 0; nt < 16; nt++) {
                int np = nt >> 1, sel = nt & 1;
                mma_f16(sc_[nt], a, bh[np][sel], bh[np][sel + 2]);
            }
        }

        float rmax0 = -1e30f, rmax1 = -1e30f;
#pragma unroll
        for (int nt = 0; nt < 16; nt++) {
            int cbase = nt * 8 + (lane & 3) * 2;
            float mk0 = maskS[cbase], mk1 = maskS[cbase + 1];
            sc_[nt][0] = fmaf(sc_[nt][0], 0.125f, mk0);
            sc_[nt][1] = fmaf(sc_[nt][1], 0.125f, mk1);
            sc_[nt][2] = fmaf(sc_[nt][2], 0.125f, mk0);
            sc_[nt][3] = fmaf(sc_[nt][3], 0.125f, mk1);
            rmax0 = fmaxf(rmax0, fmaxf(sc_[nt][0], sc_[nt][1]));
            rmax1 = fmaxf(rmax1, fmaxf(sc_[nt][2], sc_[nt][3]));
        }
        rmax0 = fmaxf(rmax0, __shfl_xor_sync(0xffffffffu, rmax0, 1));
        rmax0 = fmaxf(rmax0, __shfl_xor_sync(0xffffffffu, rmax0, 2));
        rmax1 = fmaxf(rmax1, __shfl_xor_sync(0xffffffffu, rmax1, 1));
        rmax1 = fmaxf(rmax1, __shfl_xor_sync(0xffffffffu, rmax1, 2));

        float mn0 = fmaxf(m0, rmax0), mn1 = fmaxf(m1, rmax1);
        float f0 = fexp(m0 - mn0), f1 = fexp(m1 - mn1);
        float rs0 = 0.f, rs1 = 0.f;
#pragma unroll
        for (int nt = 0; nt < 16; nt++) {
            sc_[nt][0] = fexp(sc_[nt][0] - mn0);
            sc_[nt][1] = fexp(sc_[nt][1] - mn0);
            sc_[nt][2] = fexp(sc_[nt][2] - mn1);
            sc_[nt][3] = fexp(sc_[nt][3] - mn1);
            rs0 += sc_[nt][0] + sc_[nt][1];
            rs1 += sc_[nt][2] + sc_[nt][3];
        }
        rs0 += __shfl_xor_sync(0xffffffffu, rs0, 1);
        rs0 += __shfl_xor_sync(0xffffffffu, rs0, 2);
        rs1 += __shfl_xor_sync(0xffffffffu, rs1, 1);
        rs1 += __shfl_xor_sync(0xffffffffu, rs1, 2);
        l0 = l0 * f0 + rs0;
        l1 = l1 * f1 + rs1;
        m0 = mn0; m1 = mn1;
#pragma unroll
        for (int od = 0; od < 8; od++) {
            Oa[od][0] *= f0; Oa[od][1] *= f0;
            Oa[od][2] *= f1; Oa[od][3] *= f1;
        }

        // P @ V: single-fp16 P
#pragma unroll
        for (int ks2 = 0; ks2 < 8; ks2++) {
            u32 aP[4];
            aP[0] = pack_h2(sc_[2*ks2][0],   sc_[2*ks2][1]);
            aP[1] = pack_h2(sc_[2*ks2][2],   sc_[2*ks2][3]);
            aP[2] = pack_h2(sc_[2*ks2+1][0], sc_[2*ks2+1][1]);
            aP[3] = pack_h2(sc_[2*ks2+1][2], sc_[2*ks2+1][3]);

            const u32 vr = (u32)(ks2 * 16) + frag_row;
#pragma unroll
            for (int nd = 0; nd < 4; nd++) {
                const u32 cByte = (u32)(nd * 32) + frag_col;
                u32 v0, v1, v2, v3;
                ldsm4t(sb + A_V + vr * 144 + cByte, v0, v1, v2, v3);
                mma_f16(Oa[nd * 2],     aP, v0, v1);
                mma_f16(Oa[nd * 2 + 1], aP, v2, v3);
            }
        }
    }

    float inv0 = 1.f / l0, inv1 = 1.f / l1;
    int qa = q0 + w * 16 + (lane >> 2);
    int qb2 = qa + 8;
    size_t baseA = (size_t)(b * T_ + qa) * D_ + h * DH_;
    size_t baseB = (size_t)(b * T_ + qb2) * D_ + h * DH_;
#pragma unroll
    for (int od = 0; od < 8; od++) {
        int col = od * 8 + (lane & 3) * 2;
        *(u32*)(ctxH + baseA + col) = pack_h2(Oa[od][0] * inv0, Oa[od][1] * inv0);
        *(u32*)(ctxH + baseB + col) = pack_h2(Oa[od][2] * inv1, Oa[od][3] * inv1);
    }
}

// ---------------- residual + LayerNorm ---------------------------------------
__global__ __launch_bounds__(256)
void ln_kernel(const float* __restrict__ raw,
               const float* __restrict__ rw, const float* __restrict__ re,
               const float* __restrict__ rfull, int use_full,
               const float* __restrict__ gm, const float* __restrict__ bt,
               float* __restrict__ out, int final_mode,
               half* __restrict__ outH)
{
    const int row = blockIdx.x;
    const int b = row / T_, t = row % T_;
    const float* rp = use_full
        ? rfull + (size_t)row * D_
        : (t < S_ ? rw + ((size_t)(b * S_ + t)) * D_
                  : re + ((size_t)(b * E_ + t - S_)) * D_);
    const float* x = raw + (size_t)row * D_;

    float vv[3];
    float s = 0.f, sq = 0.f;
#pragma unroll
    for (int i = 0; i < 3; i++) {
        int c = threadIdx.x + i * 256;
        float val = x[c] + rp[c];
        vv[i] = val;
        s += val;
        sq += val * val;
    }
    const int lane = threadIdx.x & 31, w = threadIdx.x >> 5;
#pragma unroll
    for (int o = 16; o; o >>= 1) {
        s  += __shfl_xor_sync(0xffffffffu, s,  o);
        sq += __shfl_xor_sync(0xffffffffu, sq, o);
    }
    __shared__ float ws[8], wq[8];
    __shared__ float sm, sv;
    if (lane == 0) { ws[w] = s; wq[w] = sq; }
    __syncthreads();
    if (threadIdx.x == 0) {
        float ts = 0.f, tq = 0.f;
#pragma unroll
        for (int i = 0; i < 8; i++) { ts += ws[i]; tq += wq[i]; }
        float mean = ts * (1.f / D_);
        sm = mean;
        sv = rsqrtf(tq * (1.f / D_) - mean * mean + 1e-12f);
    }
    __syncthreads();
    const float mean = sm, inv = sv;

    float* o = final_mode
        ? (t < S_ ? out + ((size_t)(b * S_ + t)) * D_
                  : out + (size_t)B_ * S_ * D_ + ((size_t)(b * E_ + t - S_)) * D_)
        : out + (size_t)row * D_;
#pragma unroll
    for (int i = 0; i < 3; i++) {
        int c = threadIdx.x + i * 256;
        float y = (vv[i] - mean) * inv * gm[c] + bt[c];
        o[c] = y;
        if (outH)
            outH[(size_t)row * D_ + c] = __float2half_rn(y);
    }
}

// ---------------- host -------------------------------------------------------
extern "C" void kernel_launch(void* const* d_in, const int* in_sizes, int n_in,
                              void* d_out, int out_size)
{
    const float* word  = (const float*)d_in[0];
    const float* ent   = (const float*)d_in[1];
    const float* mask  = (const float*)d_in[2];
    const float* W_q   = (const float*)d_in[3],  *b_q    = (const float*)d_in[4];
    const float* W_k   = (const float*)d_in[5],  *b_k    = (const float*)d_in[6];
    const float* W_v   = (const float*)d_in[7],  *b_v    = (const float*)d_in[8];
    const float* W_w2e = (const float*)d_in[9],  *b_w2e  = (const float*)d_in[10];
    const float* W_e2w = (const float*)d_in[11], *b_e2w  = (const float*)d_in[12];
    const float* W_e2e = (const float*)d_in[13], *b_e2e  = (const float*)d_in[14];
    const float* W_ao  = (const float*)d_in[15], *b_ao   = (const float*)d_in[16];
    const float* gm_ao = (const float*)d_in[17], *bt_ao  = (const float*)d_in[18];
    const float* W_i   = (const float*)d_in[19], *b_i    = (const float*)d_in[20];
    const float* W_o   = (const float*)d_in[21], *b_o    = (const float*)d_in[22];
    const float* gm_o  = (const float*)d_in[23], *bt_o   = (const float*)d_in[24];

    void* p;
    cudaGetSymbolAddress(&p, g_ao);    float* d_ao  = (float*)p;
    cudaGetSymbolAddress(&p, g_tmp);   float* d_tmp = (float*)p;

    half *wordF,*entF,*q1F,*q2F,*kH,*vH,*ctxF,*aoF,*intF;
    cudaGetSymbolAddress(&p, g_word); wordF = (half*)p;
    cudaGetSymbolAddress(&p, g_ent);  entF  = (half*)p;
    cudaGetSymbolAddress(&p, g_q1);   q1F   = (half*)p;
    cudaGetSymbolAddress(&p, g_q2);   q2F   = (half*)p;
    cudaGetSymbolAddress(&p, g_kh);   kH    = (half*)p;
    cudaGetSymbolAddress(&p, g_vh);   vH    = (half*)p;
    cudaGetSymbolAddress(&p, g_ctx);  ctxF  = (half*)p;
    cudaGetSymbolAddress(&p, g_aoh);  aoF   = (half*)p;
    cudaGetSymbolAddress(&p, g_int);  intF  = (half*)p;

    half *wpw,*wpe,*wao,*wi,*wo;
    cudaGetSymbolAddress(&p, g_wpw); wpw = (half*)p;
    cudaGetSymbolAddress(&p, g_wpe); wpe = (half*)p;
    cudaGetSymbolAddress(&p, g_wao); wao = (half*)p;
    cudaGetSymbolAddress(&p, g_wi);  wi  = (half*)p;
    cudaGetSymbolAddress(&p, g_wo);  wo  = (half*)p;

    cudaFuncSetAttribute(gemm_tc, cudaFuncAttributeMaxDynamicSharedMemorySize, SMEM_DYN);
    cudaFuncSetAttribute(attn_tc, cudaFuncAttributeMaxDynamicSharedMemorySize, ATT_SMEM);

    const dim3 thr(256);
    const int MW = B_ * S_;
    const int ME = B_ * E_;
    const size_t WSLICE = (size_t)D_ * D_;

    // batched 768x768 weight conversions
    WBatch9 wb;
    wb.src[0] = W_q;   wb.dst[0] = wpw + 0*WSLICE;
    wb.src[1] = W_w2e; wb.dst[1] = wpw + 1*WSLICE;
    wb.src[2] = W_k;   wb.dst[2] = wpw + 2*WSLICE;
    wb.src[3] = W_v;   wb.dst[3] = wpw + 3*WSLICE;
    wb.src[4] = W_e2w; wb.dst[4] = wpe + 0*WSLICE;
    wb.src[5] = W_e2e; wb.dst[5] = wpe + 1*WSLICE;
    wb.src[6] = W_k;   wb.dst[6] = wpe + 2*WSLICE;
    wb.src[7] = W_v;   wb.dst[7] = wpe + 3*WSLICE;
    wb.src[8] = W_ao;  wb.dst[8] = wao;
    wconv9<<<dim3(D_/32, D_/32, 9), thr>>>(wb);
    wconv<<<dim3(FF_/32, D_/32),  thr>>>(W_i, wi, D_,  FF_);
    wconv<<<dim3(D_/32,  FF_/32), thr>>>(W_o, wo, FF_, D_);

    aconv<<<(unsigned)((size_t)MW * D_ / 256), thr>>>(word, wordF);
    aconv<<<(unsigned)((size_t)ME * D_ / 256), thr>>>(ent,  entF);

    // packed projections (word + entity), interleaved into [B,T,D]
    Dest4 dpW;
    dpW.d[0] = { nullptr, q1F, nullptr, b_q   };
    dpW.d[1] = { nullptr, q2F, nullptr, b_w2e };
    dpW.d[2] = { nullptr, kH,  nullptr, b_k   };
    dpW.d[3] = { nullptr, vH,  nullptr, b_v   };
    gemm_tc<<<dim3(4*D_/128, MW/128), thr, SMEM_DYN>>>(wordF, wpw,
        dpW, MW, 4*D_, D_, D_, S_, 0, 2);

    Dest4 dpE;
    dpE.d[0] = { nullptr, q1F, nullptr, b_e2w };
    dpE.d[1] = { nullptr, q2F, nullptr, b_e2e };
    dpE.d[2] = { nullptr, kH,  nullptr, b_k   };
    dpE.d[3] = { nullptr, vH,  nullptr, b_v   };
    gemm_tc<<<dim3(4*D_/128, ME/128), thr, SMEM_DYN>>>(entF, wpe,
        dpE, ME, 4*D_, D_, D_, E_, S_, 2);

    // attention -> fp16 ctx
    attn_tc<<<dim3(T_/128, H_, B_), thr, ATT_SMEM>>>(q1F, q2F, kH, vH,
                                                     mask, ctxF);

    // AO projection + LN (LN emits fp16 ao for FFN1)
    Dest4 dpA;
    dpA.d[0] = { d_tmp, nullptr, nullptr, b_ao };
    dpA.d[1] = dpA.d[0]; dpA.d[2] = dpA.d[0]; dpA.d[3] = dpA.d[0];
    gemm_tc<<<dim3(D_/128, NT_/128), thr, SMEM_DYN>>>(ctxF, wao,
        dpA, NT_, D_, D_, D_, NT_, 0, 0);
    ln_kernel<<<NT_, thr>>>(d_tmp, word, ent, d_ao, 0, gm_ao, bt_ao, d_ao, 0, aoF);

    // FFN1 (+GELU, fp16 out)
    Dest4 dpI;
    dpI.d[0] = { nullptr, intF, nullptr, b_i };
    dpI.d[1] = dpI.d[0]; dpI.d[2] = dpI.d[0]; dpI.d[3] = dpI.d[0];
    gemm_tc<<<dim3(FF_/128, NT_/128), thr, SMEM_DYN>>>(aoF, wi,
        dpI, NT_, FF_, D_, FF_, NT_, 0, 1);

    // FFN2
    Dest4 dpO;
    dpO.d[0] = { d_tmp, nullptr, nullptr, b_o };
    dpO.d[1] = dpO.d[0]; dpO.d[2] = dpO.d[0]; dpO.d[3] = dpO.d[0];
    gemm_tc<<<dim3(D_/128, NT_/128), thr, SMEM_DYN>>>(intF, wo,
        dpO, NT_, D_, FF_, D_, NT_, 0, 0);

    // final LN -> split (word, entity) output
    ln_kernel<<<NT_, thr>>>(d_tmp, nullptr, nullptr, d_ao, 1, gm_o, bt_o,
                            (float*)d_out, 1, nullptr);
}